// round 14
// baseline (speedup 1.0000x reference)
#include <cuda_runtime.h>
#include <cuda_fp16.h>
#include <cstdint>

// ---------------- problem constants ----------------
#define BATCH 16
#define TT    100
#define W_IN  132
#define H1    159
#define H4    132
#define PLANE (H1*W_IN)     // 20988  (== 4 mod 8)
#define FEAT  (H4*W_IN)     // 17424
#define HID   100
#define NC    14
#define NL    3

// conv HMMA geometry: CTA 112(m) x 128(n), 192 threads, 6 warps in 3(m:48/48/16)x2(n:64)
#define NCH_CHUNK 25
#define CONV_NTILE 137      // ceil(17424/128)
#define A_ST 28672          // 112 rows * 256 B
#define B_ST 28672          // 112 rows * 256 B
#define CSTG (A_ST + B_ST)  // 57344
#define CONV_SMEM (2*CSTG)  // 114688

// xw HMMA geometry: split-K 7, 39 chunks of 64 (273 CTAs = 1 wave)
#define XW_SPLITK 7
#define XW_SMEM 65536

// prep1 fused-launch block ranges
#define CVT_BLOCKS 16398
#define C21_BLOCKS 40

// ---------------- scratch ----------------
__device__ float g_W21[100*100*20];
__device__ float g_W321p[4*100*2800];
__device__ float g_beff[100];
__device__ __align__(16) __half g_xh [(size_t)BATCH*100*PLANE + 512];
__device__ __align__(16) __half g_xh4[(size_t)BATCH*100*PLANE + 512];
__device__ __align__(16) __half g_wihh[(size_t)384*FEAT];
__device__ __align__(16) __half g_Aimg[(size_t)NCH_CHUNK*A_ST/2];
__device__ __align__(16) __half g_c3h[(size_t)BATCH*TT*FEAT];
__device__ float g_xwp[(size_t)XW_SPLITK*1600*384];

// ---------------- async-copy helpers ----------------
__device__ __forceinline__ void cp16(void* s, const void* g) {
    unsigned sa = (unsigned)__cvta_generic_to_shared(s);
    asm volatile("cp.async.ca.shared.global [%0], [%1], 16;" :: "r"(sa), "l"(g));
}
__device__ __forceinline__ void cp16z(void* s, const void* g, unsigned sz) {
    unsigned sa = (unsigned)__cvta_generic_to_shared(s);
    asm volatile("cp.async.ca.shared.global [%0], [%1], 16, %2;" :: "r"(sa), "l"(g), "r"(sz));
}

// ---------------- HMMA helpers ----------------
__device__ __forceinline__ void ldsm_x4(uint32_t& r0, uint32_t& r1, uint32_t& r2, uint32_t& r3,
                                        uint32_t addr) {
    asm volatile("ldmatrix.sync.aligned.m8n8.x4.shared.b16 {%0,%1,%2,%3}, [%4];"
                 : "=r"(r0), "=r"(r1), "=r"(r2), "=r"(r3) : "r"(addr));
}
__device__ __forceinline__ void ldsm_x4t(uint32_t& r0, uint32_t& r1, uint32_t& r2, uint32_t& r3,
                                         uint32_t addr) {
    asm volatile("ldmatrix.sync.aligned.m8n8.x4.trans.shared.b16 {%0,%1,%2,%3}, [%4];"
                 : "=r"(r0), "=r"(r1), "=r"(r2), "=r"(r3) : "r"(addr));
}
__device__ __forceinline__ void mma16816(float* c, uint32_t a0, uint32_t a1, uint32_t a2,
                                         uint32_t a3, uint32_t b0, uint32_t b1) {
    asm volatile(
        "mma.sync.aligned.m16n8k16.row.col.f32.f16.f16.f32 "
        "{%0,%1,%2,%3}, {%4,%5,%6,%7}, {%8,%9}, {%0,%1,%2,%3};"
        : "+f"(c[0]), "+f"(c[1]), "+f"(c[2]), "+f"(c[3])
        : "r"(a0), "r"(a1), "r"(a2), "r"(a3), "r"(b0), "r"(b1));
}

// ================= Launch 1: fused cvt_x(+shifted copy) + compose21 + fold_bias =================
__global__ __launch_bounds__(256)
void prep1(const float* __restrict__ x, __half* __restrict__ xh, __half* __restrict__ xh4,
           const float* __restrict__ w1, const float* __restrict__ w2,
           const float* __restrict__ w3,
           const float* __restrict__ bc1, const float* __restrict__ bc2,
           const float* __restrict__ bc3,
           float* __restrict__ W21, float* __restrict__ beff) {
    const int blk = blockIdx.x;
    if (blk < CVT_BLOCKS) {
        const size_t N = (size_t)BATCH * 100 * PLANE;
        size_t idx = ((size_t)blk * 256 + threadIdx.x) * 8;
        if (idx >= N + 512) return;
        uint4 out0, out4;
        if (idx < N) {
            float4 a = *(const float4*)(x + idx);
            float4 b = *(const float4*)(x + idx + 4);
            __half2 h0 = __floats2half2_rn(a.x, a.y);
            __half2 h1 = __floats2half2_rn(a.z, a.w);
            __half2 h2 = __floats2half2_rn(b.x, b.y);
            __half2 h3 = __floats2half2_rn(b.z, b.w);
            out0.x = *(uint32_t*)&h0; out0.y = *(uint32_t*)&h1;
            out0.z = *(uint32_t*)&h2; out0.w = *(uint32_t*)&h3;
            if (idx + 12 <= N) {
                float4 c = *(const float4*)(x + idx + 8);
                __half2 g0 = __floats2half2_rn(b.x, b.y);
                __half2 g1 = __floats2half2_rn(b.z, b.w);
                __half2 g2 = __floats2half2_rn(c.x, c.y);
                __half2 g3 = __floats2half2_rn(c.z, c.w);
                out4.x = *(uint32_t*)&g0; out4.y = *(uint32_t*)&g1;
                out4.z = *(uint32_t*)&g2; out4.w = *(uint32_t*)&g3;
            } else {
                float v[8];
#pragma unroll
                for (int j = 0; j < 8; ++j)
                    v[j] = (idx + 4 + j < N) ? x[idx + 4 + j] : 0.f;
                __half2 g0 = __floats2half2_rn(v[0], v[1]);
                __half2 g1 = __floats2half2_rn(v[2], v[3]);
                __half2 g2 = __floats2half2_rn(v[4], v[5]);
                __half2 g3 = __floats2half2_rn(v[6], v[7]);
                out4.x = *(uint32_t*)&g0; out4.y = *(uint32_t*)&g1;
                out4.z = *(uint32_t*)&g2; out4.w = *(uint32_t*)&g3;
            }
        } else {
            out0 = make_uint4(0, 0, 0, 0);
            out4 = make_uint4(0, 0, 0, 0);
        }
        *(uint4*)(xh + idx) = out0;
        *(uint4*)(xh4 + idx) = out4;
    } else if (blk < CVT_BLOCKS + C21_BLOCKS) {
        int idx = (blk - CVT_BLOCKS) * 256 + threadIdx.x;
        if (idx >= 10000) return;
        int m = idx / 100, i = idx - m * 100;
        float acc[19];
#pragma unroll
        for (int k = 0; k < 19; ++k) acc[k] = 0.f;
        for (int j = 0; j < 100; ++j) {
            float a[10], b[10];
            const float* pa = w2 + (m * 100 + j) * 10;
            const float* pb = w1 + (j * 100 + i) * 10;
#pragma unroll
            for (int k = 0; k < 5; ++k) {
                float2 va = *(const float2*)(pa + 2 * k);
                float2 vb = *(const float2*)(pb + 2 * k);
                a[2 * k] = va.x; a[2 * k + 1] = va.y;
                b[2 * k] = vb.x; b[2 * k + 1] = vb.y;
            }
#pragma unroll
            for (int k2 = 0; k2 < 10; ++k2)
#pragma unroll
                for (int k1 = 0; k1 < 10; ++k1)
                    acc[k2 + k1] += a[k2] * b[k1];
        }
        float* out = W21 + idx * 20;
#pragma unroll
        for (int k = 0; k < 19; ++k) out[k] = acc[k];
        out[19] = 0.f;
    } else {
        __shared__ float b21s[100];
        int o = threadIdx.x;
        if (o < 100) {
            float s = bc2[o];
            for (int i = 0; i < 100; ++i) {
                const float* wr = w2 + o * 1000 + i * 10;
                float t = 0.f;
#pragma unroll
                for (int k = 0; k < 10; ++k) t += wr[k];
                s += t * bc1[i];
            }
            b21s[o] = s;
        }
        __syncthreads();
        if (o < 100) {
            float s = bc3[o];
            for (int i = 0; i < 100; ++i) {
                const float* wr = w3 + o * 1000 + i * 10;
                float t = 0.f;
#pragma unroll
                for (int k = 0; k < 10; ++k) t += wr[k];
                s += t * b21s[i];
            }
            beff[o] = s;
        }
    }
}

// ================= Launch 2: compose321 (4-way j-split, partials) =================
__global__ void compose321_sk(const float* __restrict__ w3, const float* __restrict__ W21,
                              float* __restrict__ W321p) {
    int idx = blockIdx.x * 128 + threadIdx.x;
    if (idx >= 40000) return;
    int jc = idx / 10000;
    int r = idx - jc * 10000;
    int m = r / 100, i = r - m * 100;
    float acc[28];
#pragma unroll
    for (int k = 0; k < 28; ++k) acc[k] = 0.f;
    for (int j = jc * 25; j < jc * 25 + 25; ++j) {
        float a[10], b[20];
        const float* pa = w3 + (m * 100 + j) * 10;
        const float* pb = W21 + (j * 100 + i) * 20;
#pragma unroll
        for (int k = 0; k < 5; ++k) {
            float2 va = *(const float2*)(pa + 2 * k);
            a[2 * k] = va.x; a[2 * k + 1] = va.y;
        }
#pragma unroll
        for (int k = 0; k < 5; ++k) {
            float4 vb = *(const float4*)(pb + 4 * k);
            b[4 * k] = vb.x; b[4 * k + 1] = vb.y; b[4 * k + 2] = vb.z; b[4 * k + 3] = vb.w;
        }
#pragma unroll
        for (int k3 = 0; k3 < 10; ++k3)
#pragma unroll
            for (int k1 = 0; k1 < 19; ++k1)
                acc[k3 + k1] += a[k3] * b[k1];
    }
    float* out = W321p + jc * 280000 + m * 2800 + i * 28;
#pragma unroll
    for (int k = 0; k < 28; ++k) out[k] = acc[k];
}

// ================= Launch 3: prep_A with partial-reduce folded in =================
__global__ void prep_A_red(const float* __restrict__ W321p, __half* __restrict__ Aimg) {
    int idx = blockIdx.x * 256 + threadIdx.x;
    if (idx >= NCH_CHUNK * 112 * 128) return;
    int c = idx / (112 * 128);
    int r2 = idx - c * (112 * 128);
    int m = r2 >> 7, ks = r2 & 127;
    float wv = 0.f;
    if (ks < 112 && m < 100) {
        int off = m * 2800 + c * 112 + ks;
        wv = W321p[off] + W321p[280000 + off] + W321p[560000 + off] + W321p[840000 + off];
    }
    int kb = ks * 2;
    int byte = c * A_ST + m * 256 + (((kb >> 4) ^ (m & 7)) << 4) + (kb & 15);
    Aimg[byte >> 1] = __float2half_rn(wv);
}

// ================= cvt_wih (after conv) =================
__global__ void cvt_wih(const float* __restrict__ wih, __half* __restrict__ wihh) {
    size_t v = (size_t)blockIdx.x * 256 + threadIdx.x;
    size_t idx = v * 8;
    if (idx >= (size_t)384 * FEAT) return;
    int g = (int)(idx / FEAT);
    uint4 out;
    if (g < 300) {
        float4 a = *(const float4*)(wih + idx);
        float4 b = *(const float4*)(wih + idx + 4);
        __half2 h0 = __floats2half2_rn(a.x, a.y);
        __half2 h1 = __floats2half2_rn(a.z, a.w);
        __half2 h2 = __floats2half2_rn(b.x, b.y);
        __half2 h3 = __floats2half2_rn(b.z, b.w);
        out.x = *(uint32_t*)&h0; out.y = *(uint32_t*)&h1;
        out.z = *(uint32_t*)&h2; out.w = *(uint32_t*)&h3;
    } else {
        out = make_uint4(0, 0, 0, 0);
    }
    *(uint4*)(wihh + idx) = out;
}

// ================= Launch 4: conv via HMMA — 6 warps 3(m:48/48/16)x2(n:64), hoisted staging =================
__global__ __launch_bounds__(192, 1)
void conv_hmma(const __half* __restrict__ xh, const __half* __restrict__ xh4,
               const __half* __restrict__ Aimg,
               const float* __restrict__ beff, __half* __restrict__ c3h) {
    extern __shared__ __align__(1024) char dsm[];
    const int bb = blockIdx.y;
    const int n0 = blockIdx.x * 128;
    const int tid = threadIdx.x;
    const int wid = tid >> 5, lane = tid & 31;
    const int mg = wid % 3;              // 0,1 -> 48 rows; 2 -> 16 rows
    const int ng = wid / 3;
    const int m0w = mg * 48;
    const int n0w = ng * 64;
    const int nfm = (mg == 2) ? 1 : 3;
    const uint32_t dynb = (uint32_t)__cvta_generic_to_shared(dsm);

    float acc[3][8][4];
#pragma unroll
    for (int a = 0; a < 3; ++a)
#pragma unroll
        for (int b = 0; b < 8; ++b)
#pragma unroll
            for (int q = 0; q < 4; ++q) acc[a][b][q] = 0.f;

    const __half* xb  = xh  + (size_t)bb * 100 * PLANE;
    const __half* xb4 = xh4 + (size_t)bb * 100 * PLANE;

    // --- hoisted B staging descriptors (per thread, constant across chunks) ---
    // each chunk: 1792 cp16 over 192 threads -> up to 10 guarded iters
    const __half* b_src[10];
    int b_dst[10];
#pragma unroll
    for (int i = 0; i < 10; ++i) {
        int q = tid + i * 192;
        if (q < 1792) {
            int r = q >> 4, j = q & 15;
            int chq = r / 28, tap = r - chq * 28;
            int inplane = n0 + 132 * tap + j * 8;
            const __half* sel = ((chq + tap) & 1) ? (xb4 - 4) : xb;
            b_src[i] = sel + (size_t)chq * PLANE + inplane;
            b_dst[i] = r * 256 + ((j ^ (r & 7)) << 4);
        } else {
            b_src[i] = nullptr; b_dst[i] = 0;
        }
    }

#define CSTAGE(CC, SS) do {                                                    \
    const __half* asrc = Aimg + (size_t)(CC) * (A_ST / 2);                     \
    char* ad = dsm + (SS) * CSTG;                                              \
    _Pragma("unroll")                                                          \
    for (int i = 0; i < 10; ++i) {                                             \
        int q = tid + i * 192;                                                 \
        if (q < 1792) cp16(ad + q * 16, asrc + q * 8);                         \
    }                                                                          \
    char* bd = dsm + (SS) * CSTG + A_ST;                                       \
    const size_t cb = (size_t)(CC) * 4 * PLANE;                                \
    _Pragma("unroll")                                                          \
    for (int i = 0; i < 10; ++i) {                                             \
        if (b_src[i]) cp16(bd + b_dst[i], b_src[i] + cb);                      \
    }                                                                          \
} while (0)

    CSTAGE(0, 0);
    asm volatile("cp.async.commit_group;" ::: "memory");

    for (int c = 0; c < NCH_CHUNK; ++c) {
        const int s = c & 1;
        if (c + 1 < NCH_CHUNK) {
            CSTAGE(c + 1, 1 - s);
            asm volatile("cp.async.commit_group;" ::: "memory");
            asm volatile("cp.async.wait_group 1;" ::: "memory");
        } else {
            asm volatile("cp.async.wait_group 0;" ::: "memory");
        }
        __syncthreads();

        const uint32_t Ab = dynb + s * CSTG;
        const uint32_t Bb = Ab + A_ST;
#pragma unroll
        for (int kf = 0; kf < 7; ++kf) {
            const int k0 = kf * 16;
            uint32_t a[3][4];
#pragma unroll
            for (int fm = 0; fm < 3; ++fm) {
                if (fm < nfm) {
                    int mrow = m0w + fm * 16 + (lane & 7) + ((lane >> 3) & 1) * 8;
                    int grp = (k0 >> 3) + (lane >> 4);
                    ldsm_x4(a[fm][0], a[fm][1], a[fm][2], a[fm][3],
                            Ab + mrow * 256 + ((grp ^ (mrow & 7)) << 4));
                }
            }
            uint32_t b[8][2];
#pragma unroll
            for (int p = 0; p < 4; ++p) {
                int krow = k0 + (lane & 7) + ((lane >> 3) & 1) * 8;
                int ngi = (n0w >> 3) + p * 2 + (lane >> 4);
                ldsm_x4t(b[p * 2][0], b[p * 2][1], b[p * 2 + 1][0], b[p * 2 + 1][1],
                         Bb + krow * 256 + ((ngi ^ (krow & 7)) << 4));
            }
#pragma unroll
            for (int fm = 0; fm < 3; ++fm) {
                if (fm < nfm) {
#pragma unroll
                    for (int fn = 0; fn < 8; ++fn)
                        mma16816(acc[fm][fn], a[fm][0], a[fm][1], a[fm][2], a[fm][3],
                                 b[fn][0], b[fn][1]);
                }
            }
        }
        __syncthreads();
    }

    // epilogue: bias + fp16 store
#pragma unroll
    for (int fm = 0; fm < 3; ++fm) {
        if (fm >= nfm) continue;
        int mlo = m0w + fm * 16 + (lane >> 2);
        int mhi = mlo + 8;
        float blo = (mlo < 100) ? beff[mlo] : 0.f;
        float bhi = (mhi < 100) ? beff[mhi] : 0.f;
#pragma unroll
        for (int fn = 0; fn < 8; ++fn) {
            int n = n0 + n0w + fn * 8 + 2 * (lane & 3);
            if (n >= FEAT) continue;
            if (mlo < 100) {
                __half2 v = __floats2half2_rn(acc[fm][fn][0] + blo, acc[fm][fn][1] + blo);
                *(__half2*)(c3h + ((size_t)bb * 100 + mlo) * FEAT + n) = v;
            }
            if (mhi < 100) {
                __half2 v = __floats2half2_rn(acc[fm][fn][2] + bhi, acc[fm][fn][3] + bhi);
                *(__half2*)(c3h + ((size_t)bb * 100 + mhi) * FEAT + n) = v;
            }
        }
    }
#undef CSTAGE
}

// ================= Launch 6: GRU input GEMM via HMMA, split-K=7 =================
__global__ __launch_bounds__(256, 2)
void gemm_xw_hmma(const __half* __restrict__ gi, const __half* __restrict__ wihh,
                  float* __restrict__ xwp) {
    extern __shared__ __align__(1024) char dsm[];
    const int bt0 = blockIdx.x * 128;
    const int g0  = blockIdx.y * 128;
    const int z   = blockIdx.z;
    const int kc0 = z * 2496;
    const int nch = 39;
    const int tid = threadIdx.x;
    const int wid = tid >> 5, lane = tid & 31;
    const int m0w = (wid & 3) * 32;
    const int n0w = (wid >> 2) * 64;
    const uint32_t dynb = (uint32_t)__cvta_generic_to_shared(dsm);

    float acc[2][8][4];
#pragma unroll
    for (int a = 0; a < 2; ++a)
#pragma unroll
        for (int b = 0; b < 8; ++b)
#pragma unroll
            for (int q = 0; q < 4; ++q) acc[a][b][q] = 0.f;

#define XSTAGE(KC, SS) do {                                                    \
    for (int q = tid; q < 2048; q += 256) {                                    \
        int isB = q >> 10;                                                     \
        int r = (q >> 3) & 127, j = q & 7;                                     \
        int kg = (KC) + j * 8;                                                 \
        const __half* src;                                                     \
        if (!isB) {                                                            \
            int bt = bt0 + r; if (bt > 1599) bt = 1599;                        \
            src = gi + (size_t)bt * FEAT + kg;                                 \
        } else {                                                               \
            src = wihh + (size_t)(g0 + r) * FEAT + kg;                         \
        }                                                                      \
        unsigned sz = (kg < FEAT) ? 16u : 0u;                                  \
        if (!sz) src = gi;                                                     \
        char* dst = dsm + (SS) * 32768 + isB * 16384 + r * 128 +               \
                    ((j ^ (r & 7)) << 4);                                      \
        cp16z(dst, src, sz);                                                   \
    }                                                                          \
} while (0)

    XSTAGE(kc0, 0);
    asm volatile("cp.async.commit_group;" ::: "memory");

    for (int c = 0; c < nch; ++c) {
        const int s = c & 1;
        if (c + 1 < nch) {
            XSTAGE(kc0 + (c + 1) * 64, 1 - s);
            asm volatile("cp.async.commit_group;" ::: "memory");
            asm volatile("cp.async.wait_group 1;" ::: "memory");
        } else {
            asm volatile("cp.async.wait_group 0;" ::: "memory");
        }
        __syncthreads();

        const uint32_t Ab = dynb + s * 32768;
        const uint32_t Bb = Ab + 16384;
#pragma unroll
        for (int kf = 0; kf < 4; ++kf) {
            const int k0 = kf * 16;
            uint32_t a[2][4];
#pragma unroll
            for (int fm = 0; fm < 2; ++fm) {
                int mrow = m0w + fm * 16 + (lane & 7) + ((lane >> 3) & 1) * 8;
                int grp = (k0 >> 3) + (lane >> 4);
                ldsm_x4(a[fm][0], a[fm][1], a[fm][2], a[fm][3],
                        Ab + mrow * 128 + (((grp ^ (mrow & 7)) & 7) << 4));
            }
            uint32_t b[8][2];
#pragma unroll
            for (int p = 0; p < 4; ++p) {
                int nrow = n0w + p * 16 + ((lane >> 4) & 1) * 8 + (lane & 7);
                int grp = (k0 >> 3) + ((lane >> 3) & 1);
                ldsm_x4(b[p * 2][0], b[p * 2][1], b[p * 2 + 1][0], b[p * 2 + 1][1],
                        Bb + nrow * 128 + (((grp ^ (nrow & 7)) & 7) << 4));
            }
#pragma unroll
            for (int fm = 0; fm < 2; ++fm)
#pragma unroll
                for (int fn = 0; fn < 8; ++fn)
                    mma16816(acc[fm][fn], a[fm][0], a[fm][1], a[fm][2], a[fm][3],
                             b[fn][0], b[fn][1]);
        }
        __syncthreads();
    }

    float* outz = xwp + (size_t)z * 1600 * 384;
#pragma unroll
    for (int fm = 0; fm < 2; ++fm) {
        int mlo = bt0 + m0w + fm * 16 + (lane >> 2);
        int mhi = mlo + 8;
#pragma unroll
        for (int fn = 0; fn < 8; ++fn) {
            int n = g0 + n0w + fn * 8 + 2 * (lane & 3);
            if (mlo < 1600)
                *(float2*)(outz + (size_t)mlo * 384 + n) =
                    make_float2(acc[fm][fn][0], acc[fm][fn][1]);
            if (mhi < 1600)
                *(float2*)(outz + (size_t)mhi * 384 + n) =
                    make_float2(acc[fm][fn][2], acc[fm][fn][3]);
        }
    }
#undef XSTAGE
}

// ================= Launch 7: GRU + heads, split-K reduce fused =================
__global__ __launch_bounds__(320, 1)
void gru_kernel(const float* __restrict__ xwp, const float* __restrict__ bih,
                const float* __restrict__ whh, const float* __restrict__ bhh,
                const float* __restrict__ wy1, const float* __restrict__ by1,
                const float* __restrict__ wy2, const float* __restrict__ by2,
                float* __restrict__ out) {
    const int b = blockIdx.x;
    const int tid = threadIdx.x;
    __shared__ float h_s[HID];
    __shared__ float gh_s[3 * HID];
    __shared__ float xw_s[2][3 * HID];
    __shared__ float wy_s[(NC + NL) * HID];
    __shared__ float by_s[NC + NL];

    for (int j = tid; j < NC * HID; j += 320) wy_s[j] = wy1[j];
    for (int j = tid; j < NL * HID; j += 320) wy_s[NC * HID + j] = wy2[j];
    if (tid < NC) by_s[tid] = by1[tid];
    else if (tid < NC + NL) by_s[tid] = by2[tid - NC];
    if (tid < HID) h_s[tid] = 0.f;

    float wreg[HID];
    float bh = 0.f, bxw = 0.f;
    if (tid < 3 * HID) {
        const float4* wrow = (const float4*)(whh + (size_t)tid * HID);
#pragma unroll
        for (int j = 0; j < HID / 4; ++j) {
            float4 v = wrow[j];
            wreg[4 * j] = v.x; wreg[4 * j + 1] = v.y;
            wreg[4 * j + 2] = v.z; wreg[4 * j + 3] = v.w;
        }
        bh = bhh[tid];
        bxw = bih[tid];
        const float* base = xwp + (size_t)(b * TT + 0) * 384 + tid;
        float s = bxw;
#pragma unroll
        for (int p = 0; p < XW_SPLITK; ++p) s += base[(size_t)p * 1600 * 384];
        xw_s[0][tid] = s;
    }
    __syncthreads();

    float* y1o = out + (size_t)b * TT * NC;
    float* y2o = out + (size_t)BATCH * TT * NC + (size_t)b * TT * NL;

    for (int t = 0; t < TT; ++t) {
        float pf[XW_SPLITK];
        if (tid < 3 * HID) {
            float s0 = 0.f, s1 = 0.f, s2 = 0.f, s3 = 0.f;
#pragma unroll
            for (int j = 0; j < HID; j += 4) {
                s0 += wreg[j]     * h_s[j];
                s1 += wreg[j + 1] * h_s[j + 1];
                s2 += wreg[j + 2] * h_s[j + 2];
                s3 += wreg[j + 3] * h_s[j + 3];
            }
            gh_s[tid] = bh + ((s0 + s1) + (s2 + s3));
            if (t + 1 < TT) {
                const float* base = xwp + (size_t)(b * TT + t + 1) * 384 + tid;
#pragma unroll
                for (int p = 0; p < XW_SPLITK; ++p) pf[p] = base[(size_t)p * 1600 * 384];
            }
        } else if (t > 0 && tid < 300 + NC + NL) {
            int c = tid - 300;
            float s = by_s[c];
            const float* wr = &wy_s[c * HID];
#pragma unroll 4
            for (int j = 0; j < HID; ++j) s += wr[j] * h_s[j];
            if (c < NC) y1o[(t - 1) * NC + c] = 1.f / (1.f + expf(-s));
            else        y2o[(t - 1) * NL + (c - NC)] = tanhf(s) * 10.f;
        }
        __syncthreads();
        if (tid < HID) {
            const float* xwt = xw_s[t & 1];
            float ghr = gh_s[tid], ghz = gh_s[HID + tid], ghn = gh_s[2 * HID + tid];
            float xr = xwt[tid], xz = xwt[HID + tid], xn = xwt[2 * HID + tid];
            float r = 1.f / (1.f + expf(-(xr + ghr)));
            float z = 1.f / (1.f + expf(-(xz + ghz)));
            float n = tanhf(xn + r * ghn);
            h_s[tid] = (1.f - z) * n + z * h_s[tid];
        }
        if (tid < 3 * HID && t + 1 < TT) {
            float s = bxw;
#pragma unroll
            for (int p = 0; p < XW_SPLITK; ++p) s += pf[p];
            xw_s[(t + 1) & 1][tid] = s;
        }
        __syncthreads();
    }
    if (tid >= 300 && tid < 300 + NC + NL) {
        int c = tid - 300;
        float s = by_s[c];
        const float* wr = &wy_s[c * HID];
#pragma unroll 4
        for (int j = 0; j < HID; ++j) s += wr[j] * h_s[j];
        if (c < NC) y1o[(TT - 1) * NC + c] = 1.f / (1.f + expf(-s));
        else        y2o[(TT - 1) * NL + (c - NC)] = tanhf(s) * 10.f;
    }
}

// ---------------- launch ----------------
extern "C" void kernel_launch(void* const* d_in, const int* in_sizes, int n_in,
                              void* d_out, int out_size) {
    const float* x    = (const float*)d_in[0];
    const float* w1   = (const float*)d_in[1];
    const float* bc1  = (const float*)d_in[2];
    const float* w2   = (const float*)d_in[3];
    const float* bc2  = (const float*)d_in[4];
    const float* w3   = (const float*)d_in[5];
    const float* bc3  = (const float*)d_in[6];
    const float* w_ih = (const float*)d_in[7];
    const float* w_hh = (const float*)d_in[8];
    const float* b_ih = (const float*)d_in[9];
    const float* b_hh = (const float*)d_in[10];
    const float* w_y1 = (const float*)d_in[11];
    const float* b_y1 = (const float*)d_in[12];
    const float* w_y2 = (const float*)d_in[13];
    const float* b_y2 = (const float*)d_in[14];

    float *W21, *W321p, *beff, *xwp;
    __half *xh, *xh4, *wihh, *Aimg, *c3h;
    cudaGetSymbolAddress((void**)&W21,   g_W21);
    cudaGetSymbolAddress((void**)&W321p, g_W321p);
    cudaGetSymbolAddress((void**)&beff,  g_beff);
    cudaGetSymbolAddress((void**)&xwp,   g_xwp);
    cudaGetSymbolAddress((void**)&xh,    g_xh);
    cudaGetSymbolAddress((void**)&xh4,   g_xh4);
    cudaGetSymbolAddress((void**)&wihh,  g_wihh);
    cudaGetSymbolAddress((void**)&Aimg,  g_Aimg);
    cudaGetSymbolAddress((void**)&c3h,   g_c3h);

    cudaFuncSetAttribute(conv_hmma, cudaFuncAttributeMaxDynamicSharedMemorySize, CONV_SMEM);
    cudaFuncSetAttribute(gemm_xw_hmma, cudaFuncAttributeMaxDynamicSharedMemorySize, XW_SMEM);

    // L1: cvt_x (+ shifted copy) + compose21 + fold_bias (fused)
    prep1<<<CVT_BLOCKS + C21_BLOCKS + 1, 256>>>(x, xh, xh4, w1, w2, w3, bc1, bc2, bc3, W21, beff);
    // L2: compose321 partials
    compose321_sk<<<(40000 + 127) / 128, 128>>>(w3, W21, W321p);
    // L3: A-image build + partial reduce
    prep_A_red<<<(NCH_CHUNK * 112 * 128 + 255) / 256, 256>>>(W321p, Aimg);
    // L4: conv (profiled slot), 3x2 warp layout, hoisted staging
    conv_hmma<<<dim3(CONV_NTILE, BATCH), 192, CONV_SMEM>>>(xh, xh4, Aimg, beff, c3h);
    // L5: w_ih fp16
    size_t nwv = ((size_t)384 * FEAT) / 8;
    cvt_wih<<<(int)((nwv + 255) / 256), 256>>>(w_ih, wihh);
    // L6: GRU input GEMM (split-K partials)
    gemm_xw_hmma<<<dim3(13, 3, XW_SPLITK), 256, XW_SMEM>>>(c3h, wihh, xwp);
    // L7: GRU + heads with fused split-K reduce
    gru_kernel<<<BATCH, 320>>>(xwp, b_ih, w_hh, b_hh, w_y1, b_y1, w_y2, b_y2, (float*)d_out);
}

// round 15
// speedup vs baseline: 1.1442x; 1.1442x over previous
#include <cuda_runtime.h>
#include <cuda_fp16.h>
#include <cstdint>

// ---------------- problem constants ----------------
#define BATCH 16
#define TT    100
#define W_IN  132
#define H1    159
#define H4    132
#define PLANE (H1*W_IN)     // 20988  (== 4 mod 8)
#define FEAT  (H4*W_IN)     // 17424
#define HID   100
#define NC    14
#define NL    3

// conv HMMA geometry: CTA 112(m) x 256(n), 256 threads, 8 warps in 4(m:32/32/32/16)x2(n:128)
#define NCH_CHUNK 25
#define CONV_NTILE 69       // ceil(17424/256)
#define A_ST 28672          // 112 k-rows * 256 B (A: m x k image)
#define B_ST 57344          // 112 k-rows * 512 B (B: k x 256n)
#define CSTG (A_ST + B_ST)  // 86016
#define CONV_SMEM (2*CSTG)  // 172032

// xw HMMA geometry: split-K 7, 39 chunks of 64 (273 CTAs = 1 wave)
#define XW_SPLITK 7
#define XW_SMEM 65536

// prep1 fused-launch block ranges
#define CVT_BLOCKS 16398
#define C21_BLOCKS 40

// ---------------- scratch ----------------
__device__ float g_W21[100*100*20];
__device__ float g_W321p[4*100*2800];
__device__ float g_beff[100];
__device__ __align__(16) __half g_xh [(size_t)BATCH*100*PLANE + 1024];
__device__ __align__(16) __half g_xh4[(size_t)BATCH*100*PLANE + 1024];
__device__ __align__(16) __half g_wihh[(size_t)384*FEAT];
__device__ __align__(16) __half g_Aimg[(size_t)NCH_CHUNK*A_ST/2];
__device__ __align__(16) __half g_c3h[(size_t)BATCH*TT*FEAT];
__device__ float g_xwp[(size_t)XW_SPLITK*1600*384];

// ---------------- async-copy helpers ----------------
__device__ __forceinline__ void cp16(void* s, const void* g) {
    unsigned sa = (unsigned)__cvta_generic_to_shared(s);
    asm volatile("cp.async.ca.shared.global [%0], [%1], 16;" :: "r"(sa), "l"(g));
}
__device__ __forceinline__ void cp16z(void* s, const void* g, unsigned sz) {
    unsigned sa = (unsigned)__cvta_generic_to_shared(s);
    asm volatile("cp.async.ca.shared.global [%0], [%1], 16, %2;" :: "r"(sa), "l"(g), "r"(sz));
}

// ---------------- HMMA helpers ----------------
__device__ __forceinline__ void ldsm_x4(uint32_t& r0, uint32_t& r1, uint32_t& r2, uint32_t& r3,
                                        uint32_t addr) {
    asm volatile("ldmatrix.sync.aligned.m8n8.x4.shared.b16 {%0,%1,%2,%3}, [%4];"
                 : "=r"(r0), "=r"(r1), "=r"(r2), "=r"(r3) : "r"(addr));
}
__device__ __forceinline__ void ldsm_x4t(uint32_t& r0, uint32_t& r1, uint32_t& r2, uint32_t& r3,
                                         uint32_t addr) {
    asm volatile("ldmatrix.sync.aligned.m8n8.x4.trans.shared.b16 {%0,%1,%2,%3}, [%4];"
                 : "=r"(r0), "=r"(r1), "=r"(r2), "=r"(r3) : "r"(addr));
}
__device__ __forceinline__ void mma16816(float* c, uint32_t a0, uint32_t a1, uint32_t a2,
                                         uint32_t a3, uint32_t b0, uint32_t b1) {
    asm volatile(
        "mma.sync.aligned.m16n8k16.row.col.f32.f16.f16.f32 "
        "{%0,%1,%2,%3}, {%4,%5,%6,%7}, {%8,%9}, {%0,%1,%2,%3};"
        : "+f"(c[0]), "+f"(c[1]), "+f"(c[2]), "+f"(c[3])
        : "r"(a0), "r"(a1), "r"(a2), "r"(a3), "r"(b0), "r"(b1));
}

// ================= Launch 1: fused cvt_x(+shifted copy) + compose21 + fold_bias =================
__global__ __launch_bounds__(256)
void prep1(const float* __restrict__ x, __half* __restrict__ xh, __half* __restrict__ xh4,
           const float* __restrict__ w1, const float* __restrict__ w2,
           const float* __restrict__ w3,
           const float* __restrict__ bc1, const float* __restrict__ bc2,
           const float* __restrict__ bc3,
           float* __restrict__ W21, float* __restrict__ beff) {
    const int blk = blockIdx.x;
    if (blk < CVT_BLOCKS) {
        const size_t N = (size_t)BATCH * 100 * PLANE;
        size_t idx = ((size_t)blk * 256 + threadIdx.x) * 8;
        if (idx >= N + 1024) return;
        uint4 out0, out4;
        if (idx < N) {
            float4 a = *(const float4*)(x + idx);
            float4 b = *(const float4*)(x + idx + 4);
            __half2 h0 = __floats2half2_rn(a.x, a.y);
            __half2 h1 = __floats2half2_rn(a.z, a.w);
            __half2 h2 = __floats2half2_rn(b.x, b.y);
            __half2 h3 = __floats2half2_rn(b.z, b.w);
            out0.x = *(uint32_t*)&h0; out0.y = *(uint32_t*)&h1;
            out0.z = *(uint32_t*)&h2; out0.w = *(uint32_t*)&h3;
            if (idx + 12 <= N) {
                float4 c = *(const float4*)(x + idx + 8);
                __half2 g0 = __floats2half2_rn(b.x, b.y);
                __half2 g1 = __floats2half2_rn(b.z, b.w);
                __half2 g2 = __floats2half2_rn(c.x, c.y);
                __half2 g3 = __floats2half2_rn(c.z, c.w);
                out4.x = *(uint32_t*)&g0; out4.y = *(uint32_t*)&g1;
                out4.z = *(uint32_t*)&g2; out4.w = *(uint32_t*)&g3;
            } else {
                float v[8];
#pragma unroll
                for (int j = 0; j < 8; ++j)
                    v[j] = (idx + 4 + j < N) ? x[idx + 4 + j] : 0.f;
                __half2 g0 = __floats2half2_rn(v[0], v[1]);
                __half2 g1 = __floats2half2_rn(v[2], v[3]);
                __half2 g2 = __floats2half2_rn(v[4], v[5]);
                __half2 g3 = __floats2half2_rn(v[6], v[7]);
                out4.x = *(uint32_t*)&g0; out4.y = *(uint32_t*)&g1;
                out4.z = *(uint32_t*)&g2; out4.w = *(uint32_t*)&g3;
            }
        } else {
            out0 = make_uint4(0, 0, 0, 0);
            out4 = make_uint4(0, 0, 0, 0);
        }
        *(uint4*)(xh + idx) = out0;
        *(uint4*)(xh4 + idx) = out4;
    } else if (blk < CVT_BLOCKS + C21_BLOCKS) {
        int idx = (blk - CVT_BLOCKS) * 256 + threadIdx.x;
        if (idx >= 10000) return;
        int m = idx / 100, i = idx - m * 100;
        float acc[19];
#pragma unroll
        for (int k = 0; k < 19; ++k) acc[k] = 0.f;
        for (int j = 0; j < 100; ++j) {
            float a[10], b[10];
            const float* pa = w2 + (m * 100 + j) * 10;
            const float* pb = w1 + (j * 100 + i) * 10;
#pragma unroll
            for (int k = 0; k < 5; ++k) {
                float2 va = *(const float2*)(pa + 2 * k);
                float2 vb = *(const float2*)(pb + 2 * k);
                a[2 * k] = va.x; a[2 * k + 1] = va.y;
                b[2 * k] = vb.x; b[2 * k + 1] = vb.y;
            }
#pragma unroll
            for (int k2 = 0; k2 < 10; ++k2)
#pragma unroll
                for (int k1 = 0; k1 < 10; ++k1)
                    acc[k2 + k1] += a[k2] * b[k1];
        }
        float* out = W21 + idx * 20;
#pragma unroll
        for (int k = 0; k < 19; ++k) out[k] = acc[k];
        out[19] = 0.f;
    } else {
        __shared__ float b21s[100];
        int o = threadIdx.x;
        if (o < 100) {
            float s = bc2[o];
            for (int i = 0; i < 100; ++i) {
                const float* wr = w2 + o * 1000 + i * 10;
                float t = 0.f;
#pragma unroll
                for (int k = 0; k < 10; ++k) t += wr[k];
                s += t * bc1[i];
            }
            b21s[o] = s;
        }
        __syncthreads();
        if (o < 100) {
            float s = bc3[o];
            for (int i = 0; i < 100; ++i) {
                const float* wr = w3 + o * 1000 + i * 10;
                float t = 0.f;
#pragma unroll
                for (int k = 0; k < 10; ++k) t += wr[k];
                s += t * b21s[i];
            }
            beff[o] = s;
        }
    }
}

// ================= Launch 2: compose321 (4-way j-split, partials) =================
__global__ void compose321_sk(const float* __restrict__ w3, const float* __restrict__ W21,
                              float* __restrict__ W321p) {
    int idx = blockIdx.x * 128 + threadIdx.x;
    if (idx >= 40000) return;
    int jc = idx / 10000;
    int r = idx - jc * 10000;
    int m = r / 100, i = r - m * 100;
    float acc[28];
#pragma unroll
    for (int k = 0; k < 28; ++k) acc[k] = 0.f;
    for (int j = jc * 25; j < jc * 25 + 25; ++j) {
        float a[10], b[20];
        const float* pa = w3 + (m * 100 + j) * 10;
        const float* pb = W21 + (j * 100 + i) * 20;
#pragma unroll
        for (int k = 0; k < 5; ++k) {
            float2 va = *(const float2*)(pa + 2 * k);
            a[2 * k] = va.x; a[2 * k + 1] = va.y;
        }
#pragma unroll
        for (int k = 0; k < 5; ++k) {
            float4 vb = *(const float4*)(pb + 4 * k);
            b[4 * k] = vb.x; b[4 * k + 1] = vb.y; b[4 * k + 2] = vb.z; b[4 * k + 3] = vb.w;
        }
#pragma unroll
        for (int k3 = 0; k3 < 10; ++k3)
#pragma unroll
            for (int k1 = 0; k1 < 19; ++k1)
                acc[k3 + k1] += a[k3] * b[k1];
    }
    float* out = W321p + jc * 280000 + m * 2800 + i * 28;
#pragma unroll
    for (int k = 0; k < 28; ++k) out[k] = acc[k];
}

// ================= Launch 3: prep_A with partial-reduce folded in =================
__global__ void prep_A_red(const float* __restrict__ W321p, __half* __restrict__ Aimg) {
    int idx = blockIdx.x * 256 + threadIdx.x;
    if (idx >= NCH_CHUNK * 112 * 128) return;
    int c = idx / (112 * 128);
    int r2 = idx - c * (112 * 128);
    int m = r2 >> 7, ks = r2 & 127;
    float wv = 0.f;
    if (ks < 112 && m < 100) {
        int off = m * 2800 + c * 112 + ks;
        wv = W321p[off] + W321p[280000 + off] + W321p[560000 + off] + W321p[840000 + off];
    }
    int kb = ks * 2;
    int byte = c * A_ST + m * 256 + (((kb >> 4) ^ (m & 7)) << 4) + (kb & 15);
    Aimg[byte >> 1] = __float2half_rn(wv);
}

// ================= cvt_wih (after conv) =================
__global__ void cvt_wih(const float* __restrict__ wih, __half* __restrict__ wihh) {
    size_t v = (size_t)blockIdx.x * 256 + threadIdx.x;
    size_t idx = v * 8;
    if (idx >= (size_t)384 * FEAT) return;
    int g = (int)(idx / FEAT);
    uint4 out;
    if (g < 300) {
        float4 a = *(const float4*)(wih + idx);
        float4 b = *(const float4*)(wih + idx + 4);
        __half2 h0 = __floats2half2_rn(a.x, a.y);
        __half2 h1 = __floats2half2_rn(a.z, a.w);
        __half2 h2 = __floats2half2_rn(b.x, b.y);
        __half2 h3 = __floats2half2_rn(b.z, b.w);
        out.x = *(uint32_t*)&h0; out.y = *(uint32_t*)&h1;
        out.z = *(uint32_t*)&h2; out.w = *(uint32_t*)&h3;
    } else {
        out = make_uint4(0, 0, 0, 0);
    }
    *(uint4*)(wihh + idx) = out;
}

// ================= Launch 4: conv via HMMA — CTA 112x256, 8 warps 4(m)x2(n:128) =================
__global__ __launch_bounds__(256, 1)
void conv_hmma(const __half* __restrict__ xh, const __half* __restrict__ xh4,
               const __half* __restrict__ Aimg,
               const float* __restrict__ beff, __half* __restrict__ c3h) {
    extern __shared__ __align__(1024) char dsm[];
    const int bb = blockIdx.y;
    const int n0 = blockIdx.x * 256;
    const int tid = threadIdx.x;
    const int wid = tid >> 5, lane = tid & 31;
    const int mg = wid & 3;              // m-group: 32/32/32/16 rows
    const int ng = wid >> 2;             // n-group: 0 or 1 (128 each)
    const int m0w = mg * 32;
    const int n0w = ng * 128;
    const int nfm = (mg == 3) ? 1 : 2;
    const uint32_t dynb = (uint32_t)__cvta_generic_to_shared(dsm);

    float acc[2][16][4];
#pragma unroll
    for (int a = 0; a < 2; ++a)
#pragma unroll
        for (int b = 0; b < 16; ++b)
#pragma unroll
            for (int q = 0; q < 4; ++q) acc[a][b][q] = 0.f;

    const __half* xb  = xh  + (size_t)bb * 100 * PLANE;
    const __half* xb4 = xh4 + (size_t)bb * 100 * PLANE;

    // B staging: 112 rows x 32 cp16 (512B rows), all cp16 via xh/xh4 parity trick
#define CSTAGE(CC, SS) do {                                                    \
    const __half* asrc = Aimg + (size_t)(CC) * (A_ST / 2);                     \
    char* ad = dsm + (SS) * CSTG;                                              \
    for (int q = tid; q < 1792; q += 256) cp16(ad + q * 16, asrc + q * 8);     \
    char* bd = dsm + (SS) * CSTG + A_ST;                                       \
    int c4 = (CC) * 4;                                                         \
    for (int q = tid; q < 3584; q += 256) {                                    \
        int r = q >> 5, j = q & 31;                                            \
        int chq = r / 28, tap = r - chq * 28;                                  \
        size_t base = (size_t)(c4 + chq) * PLANE + n0 + 132 * tap + j * 8;     \
        const __half* src = ((chq + tap) & 1) ? (xb4 + base - 4) : (xb + base);\
        char* dst = bd + r * 512 + ((j ^ (r & 7)) << 4);                       \
        cp16(dst, src);                                                        \
    }                                                                          \
} while (0)

    CSTAGE(0, 0);
    asm volatile("cp.async.commit_group;" ::: "memory");

    for (int c = 0; c < NCH_CHUNK; ++c) {
        const int s = c & 1;
        if (c + 1 < NCH_CHUNK) {
            CSTAGE(c + 1, 1 - s);
            asm volatile("cp.async.commit_group;" ::: "memory");
            asm volatile("cp.async.wait_group 1;" ::: "memory");
        } else {
            asm volatile("cp.async.wait_group 0;" ::: "memory");
        }
        __syncthreads();

        const uint32_t Ab = dynb + s * CSTG;
        const uint32_t Bb = Ab + A_ST;
#pragma unroll
        for (int kf = 0; kf < 7; ++kf) {
            const int k0 = kf * 16;
            uint32_t a[2][4];
#pragma unroll
            for (int fm = 0; fm < 2; ++fm) {
                if (fm < nfm) {
                    int mrow = m0w + fm * 16 + (lane & 7) + ((lane >> 3) & 1) * 8;
                    int grp = (k0 >> 3) + (lane >> 4);
                    ldsm_x4(a[fm][0], a[fm][1], a[fm][2], a[fm][3],
                            Ab + mrow * 256 + ((grp ^ (mrow & 7)) << 4));
                }
            }
            const int krow = k0 + (lane & 7) + ((lane >> 3) & 1) * 8;
            const uint32_t brow = Bb + krow * 512;
            const int ksw = krow & 7;
#pragma unroll
            for (int p = 0; p < 8; ++p) {
                uint32_t b0, b1, b2, b3;
                int ngi = (n0w >> 3) + p * 2 + (lane >> 4);
                ldsm_x4t(b0, b1, b2, b3, brow + ((ngi ^ ksw) << 4));
#pragma unroll
                for (int fm = 0; fm < 2; ++fm) {
                    if (fm < nfm) {
                        mma16816(acc[fm][p * 2],     a[fm][0], a[fm][1], a[fm][2], a[fm][3], b0, b1);
                        mma16816(acc[fm][p * 2 + 1], a[fm][0], a[fm][1], a[fm][2], a[fm][3], b2, b3);
                    }
                }
            }
        }
        __syncthreads();
    }

    // epilogue: bias + fp16 store
#pragma unroll
    for (int fm = 0; fm < 2; ++fm) {
        if (fm >= nfm) continue;
        int mlo = m0w + fm * 16 + (lane >> 2);
        int mhi = mlo + 8;
        float blo = (mlo < 100) ? beff[mlo] : 0.f;
        float bhi = (mhi < 100) ? beff[mhi] : 0.f;
#pragma unroll
        for (int fn = 0; fn < 16; ++fn) {
            int n = n0 + n0w + fn * 8 + 2 * (lane & 3);
            if (n >= FEAT) continue;
            if (mlo < 100) {
                __half2 v = __floats2half2_rn(acc[fm][fn][0] + blo, acc[fm][fn][1] + blo);
                *(__half2*)(c3h + ((size_t)bb * 100 + mlo) * FEAT + n) = v;
            }
            if (mhi < 100) {
                __half2 v = __floats2half2_rn(acc[fm][fn][2] + bhi, acc[fm][fn][3] + bhi);
                *(__half2*)(c3h + ((size_t)bb * 100 + mhi) * FEAT + n) = v;
            }
        }
    }
#undef CSTAGE
}

// ================= Launch 6: GRU input GEMM via HMMA, split-K=7 =================
__global__ __launch_bounds__(256, 2)
void gemm_xw_hmma(const __half* __restrict__ gi, const __half* __restrict__ wihh,
                  float* __restrict__ xwp) {
    extern __shared__ __align__(1024) char dsm[];
    const int bt0 = blockIdx.x * 128;
    const int g0  = blockIdx.y * 128;
    const int z   = blockIdx.z;
    const int kc0 = z * 2496;
    const int nch = 39;
    const int tid = threadIdx.x;
    const int wid = tid >> 5, lane = tid & 31;
    const int m0w = (wid & 3) * 32;
    const int n0w = (wid >> 2) * 64;
    const uint32_t dynb = (uint32_t)__cvta_generic_to_shared(dsm);

    float acc[2][8][4];
#pragma unroll
    for (int a = 0; a < 2; ++a)
#pragma unroll
        for (int b = 0; b < 8; ++b)
#pragma unroll
            for (int q = 0; q < 4; ++q) acc[a][b][q] = 0.f;

#define XSTAGE(KC, SS) do {                                                    \
    for (int q = tid; q < 2048; q += 256) {                                    \
        int isB = q >> 10;                                                     \
        int r = (q >> 3) & 127, j = q & 7;                                     \
        int kg = (KC) + j * 8;                                                 \
        const __half* src;                                                     \
        if (!isB) {                                                            \
            int bt = bt0 + r; if (bt > 1599) bt = 1599;                        \
            src = gi + (size_t)bt * FEAT + kg;                                 \
        } else {                                                               \
            src = wihh + (size_t)(g0 + r) * FEAT + kg;                         \
        }                                                                      \
        unsigned sz = (kg < FEAT) ? 16u : 0u;                                  \
        if (!sz) src = gi;                                                     \
        char* dst = dsm + (SS) * 32768 + isB * 16384 + r * 128 +               \
                    ((j ^ (r & 7)) << 4);                                      \
        cp16z(dst, src, sz);                                                   \
    }                                                                          \
} while (0)

    XSTAGE(kc0, 0);
    asm volatile("cp.async.commit_group;" ::: "memory");

    for (int c = 0; c < nch; ++c) {
        const int s = c & 1;
        if (c + 1 < nch) {
            XSTAGE(kc0 + (c + 1) * 64, 1 - s);
            asm volatile("cp.async.commit_group;" ::: "memory");
            asm volatile("cp.async.wait_group 1;" ::: "memory");
        } else {
            asm volatile("cp.async.wait_group 0;" ::: "memory");
        }
        __syncthreads();

        const uint32_t Ab = dynb + s * 32768;
        const uint32_t Bb = Ab + 16384;
#pragma unroll
        for (int kf = 0; kf < 4; ++kf) {
            const int k0 = kf * 16;
            uint32_t a[2][4];
#pragma unroll
            for (int fm = 0; fm < 2; ++fm) {
                int mrow = m0w + fm * 16 + (lane & 7) + ((lane >> 3) & 1) * 8;
                int grp = (k0 >> 3) + (lane >> 4);
                ldsm_x4(a[fm][0], a[fm][1], a[fm][2], a[fm][3],
                        Ab + mrow * 128 + (((grp ^ (mrow & 7)) & 7) << 4));
            }
            uint32_t b[8][2];
#pragma unroll
            for (int p = 0; p < 4; ++p) {
                int nrow = n0w + p * 16 + ((lane >> 4) & 1) * 8 + (lane & 7);
                int grp = (k0 >> 3) + ((lane >> 3) & 1);
                ldsm_x4(b[p * 2][0], b[p * 2][1], b[p * 2 + 1][0], b[p * 2 + 1][1],
                        Bb + nrow * 128 + (((grp ^ (nrow & 7)) & 7) << 4));
            }
#pragma unroll
            for (int fm = 0; fm < 2; ++fm)
#pragma unroll
                for (int fn = 0; fn < 8; ++fn)
                    mma16816(acc[fm][fn], a[fm][0], a[fm][1], a[fm][2], a[fm][3],
                             b[fn][0], b[fn][1]);
        }
        __syncthreads();
    }

    float* outz = xwp + (size_t)z * 1600 * 384;
#pragma unroll
    for (int fm = 0; fm < 2; ++fm) {
        int mlo = bt0 + m0w + fm * 16 + (lane >> 2);
        int mhi = mlo + 8;
#pragma unroll
        for (int fn = 0; fn < 8; ++fn) {
            int n = g0 + n0w + fn * 8 + 2 * (lane & 3);
            if (mlo < 1600)
                *(float2*)(outz + (size_t)mlo * 384 + n) =
                    make_float2(acc[fm][fn][0], acc[fm][fn][1]);
            if (mhi < 1600)
                *(float2*)(outz + (size_t)mhi * 384 + n) =
                    make_float2(acc[fm][fn][2], acc[fm][fn][3]);
        }
    }
#undef XSTAGE
}

// ================= Launch 7: GRU + heads, split-K reduce fused =================
__global__ __launch_bounds__(320, 1)
void gru_kernel(const float* __restrict__ xwp, const float* __restrict__ bih,
                const float* __restrict__ whh, const float* __restrict__ bhh,
                const float* __restrict__ wy1, const float* __restrict__ by1,
                const float* __restrict__ wy2, const float* __restrict__ by2,
                float* __restrict__ out) {
    const int b = blockIdx.x;
    const int tid = threadIdx.x;
    __shared__ float h_s[HID];
    __shared__ float gh_s[3 * HID];
    __shared__ float xw_s[2][3 * HID];
    __shared__ float wy_s[(NC + NL) * HID];
    __shared__ float by_s[NC + NL];

    for (int j = tid; j < NC * HID; j += 320) wy_s[j] = wy1[j];
    for (int j = tid; j < NL * HID; j += 320) wy_s[NC * HID + j] = wy2[j];
    if (tid < NC) by_s[tid] = by1[tid];
    else if (tid < NC + NL) by_s[tid] = by2[tid - NC];
    if (tid < HID) h_s[tid] = 0.f;

    float wreg[HID];
    float bh = 0.f, bxw = 0.f;
    if (tid < 3 * HID) {
        const float4* wrow = (const float4*)(whh + (size_t)tid * HID);
#pragma unroll
        for (int j = 0; j < HID / 4; ++j) {
            float4 v = wrow[j];
            wreg[4 * j] = v.x; wreg[4 * j + 1] = v.y;
            wreg[4 * j + 2] = v.z; wreg[4 * j + 3] = v.w;
        }
        bh = bhh[tid];
        bxw = bih[tid];
        const float* base = xwp + (size_t)(b * TT + 0) * 384 + tid;
        float s = bxw;
#pragma unroll
        for (int p = 0; p < XW_SPLITK; ++p) s += base[(size_t)p * 1600 * 384];
        xw_s[0][tid] = s;
    }
    __syncthreads();

    float* y1o = out + (size_t)b * TT * NC;
    float* y2o = out + (size_t)BATCH * TT * NC + (size_t)b * TT * NL;

    for (int t = 0; t < TT; ++t) {
        float pf[XW_SPLITK];
        if (tid < 3 * HID) {
            float s0 = 0.f, s1 = 0.f, s2 = 0.f, s3 = 0.f;
#pragma unroll
            for (int j = 0; j < HID; j += 4) {
                s0 += wreg[j]     * h_s[j];
                s1 += wreg[j + 1] * h_s[j + 1];
                s2 += wreg[j + 2] * h_s[j + 2];
                s3 += wreg[j + 3] * h_s[j + 3];
            }
            gh_s[tid] = bh + ((s0 + s1) + (s2 + s3));
            if (t + 1 < TT) {
                const float* base = xwp + (size_t)(b * TT + t + 1) * 384 + tid;
#pragma unroll
                for (int p = 0; p < XW_SPLITK; ++p) pf[p] = base[(size_t)p * 1600 * 384];
            }
        } else if (t > 0 && tid < 300 + NC + NL) {
            int c = tid - 300;
            float s = by_s[c];
            const float* wr = &wy_s[c * HID];
#pragma unroll 4
            for (int j = 0; j < HID; ++j) s += wr[j] * h_s[j];
            if (c < NC) y1o[(t - 1) * NC + c] = 1.f / (1.f + expf(-s));
            else        y2o[(t - 1) * NL + (c - NC)] = tanhf(s) * 10.f;
        }
        __syncthreads();
        if (tid < HID) {
            const float* xwt = xw_s[t & 1];
            float ghr = gh_s[tid], ghz = gh_s[HID + tid], ghn = gh_s[2 * HID + tid];
            float xr = xwt[tid], xz = xwt[HID + tid], xn = xwt[2 * HID + tid];
            float r = 1.f / (1.f + expf(-(xr + ghr)));
            float z = 1.f / (1.f + expf(-(xz + ghz)));
            float n = tanhf(xn + r * ghn);
            h_s[tid] = (1.f - z) * n + z * h_s[tid];
        }
        if (tid < 3 * HID && t + 1 < TT) {
            float s = bxw;
#pragma unroll
            for (int p = 0; p < XW_SPLITK; ++p) s += pf[p];
            xw_s[(t + 1) & 1][tid] = s;
        }
        __syncthreads();
    }
    if (tid >= 300 && tid < 300 + NC + NL) {
        int c = tid - 300;
        float s = by_s[c];
        const float* wr = &wy_s[c * HID];
#pragma unroll 4
        for (int j = 0; j < HID; ++j) s += wr[j] * h_s[j];
        if (c < NC) y1o[(TT - 1) * NC + c] = 1.f / (1.f + expf(-s));
        else        y2o[(TT - 1) * NL + (c - NC)] = tanhf(s) * 10.f;
    }
}

// ---------------- launch ----------------
extern "C" void kernel_launch(void* const* d_in, const int* in_sizes, int n_in,
                              void* d_out, int out_size) {
    const float* x    = (const float*)d_in[0];
    const float* w1   = (const float*)d_in[1];
    const float* bc1  = (const float*)d_in[2];
    const float* w2   = (const float*)d_in[3];
    const float* bc2  = (const float*)d_in[4];
    const float* w3   = (const float*)d_in[5];
    const float* bc3  = (const float*)d_in[6];
    const float* w_ih = (const float*)d_in[7];
    const float* w_hh = (const float*)d_in[8];
    const float* b_ih = (const float*)d_in[9];
    const float* b_hh = (const float*)d_in[10];
    const float* w_y1 = (const float*)d_in[11];
    const float* b_y1 = (const float*)d_in[12];
    const float* w_y2 = (const float*)d_in[13];
    const float* b_y2 = (const float*)d_in[14];

    float *W21, *W321p, *beff, *xwp;
    __half *xh, *xh4, *wihh, *Aimg, *c3h;
    cudaGetSymbolAddress((void**)&W21,   g_W21);
    cudaGetSymbolAddress((void**)&W321p, g_W321p);
    cudaGetSymbolAddress((void**)&beff,  g_beff);
    cudaGetSymbolAddress((void**)&xwp,   g_xwp);
    cudaGetSymbolAddress((void**)&xh,    g_xh);
    cudaGetSymbolAddress((void**)&xh4,   g_xh4);
    cudaGetSymbolAddress((void**)&wihh,  g_wihh);
    cudaGetSymbolAddress((void**)&Aimg,  g_Aimg);
    cudaGetSymbolAddress((void**)&c3h,   g_c3h);

    cudaFuncSetAttribute(conv_hmma, cudaFuncAttributeMaxDynamicSharedMemorySize, CONV_SMEM);
    cudaFuncSetAttribute(gemm_xw_hmma, cudaFuncAttributeMaxDynamicSharedMemorySize, XW_SMEM);

    // L1: cvt_x (+ shifted copy) + compose21 + fold_bias (fused)
    prep1<<<CVT_BLOCKS + C21_BLOCKS + 1, 256>>>(x, xh, xh4, w1, w2, w3, bc1, bc2, bc3, W21, beff);
    // L2: compose321 partials
    compose321_sk<<<(40000 + 127) / 128, 128>>>(w3, W21, W321p);
    // L3: A-image build + partial reduce
    prep_A_red<<<(NCH_CHUNK * 112 * 128 + 255) / 256, 256>>>(W321p, Aimg);
    // L4: conv (profiled slot), 112x256 CTA, warp n=128
    conv_hmma<<<dim3(CONV_NTILE, BATCH), 256, CONV_SMEM>>>(xh, xh4, Aimg, beff, c3h);
    // L5: w_ih fp16
    size_t nwv = ((size_t)384 * FEAT) / 8;
    cvt_wih<<<(int)((nwv + 255) / 256), 256>>>(w_ih, wihh);
    // L6: GRU input GEMM (split-K partials)
    gemm_xw_hmma<<<dim3(13, 3, XW_SPLITK), 256, XW_SMEM>>>(c3h, wihh, xwp);
    // L7: GRU + heads with fused split-K reduce
    gru_kernel<<<BATCH, 320>>>(xwp, b_ih, w_hh, b_hh, w_y1, b_y1, w_y2, b_y2, (float*)d_out);
}

// round 16
// speedup vs baseline: 1.1486x; 1.0038x over previous
#include <cuda_runtime.h>
#include <cuda_fp16.h>
#include <cstdint>

// ---------------- problem constants ----------------
#define BATCH 16
#define TT    100
#define W_IN  132
#define H1    159
#define H4    132
#define PLANE (H1*W_IN)     // 20988  (== 4 mod 8)
#define FEAT  (H4*W_IN)     // 17424
#define HID   100
#define NC    14
#define NL    3

// conv HMMA geometry: CTA 112(m) x 256(n), 512 threads, 16 warps in 4(m:32/32/32/16)x4(n:64)
#define NCH_CHUNK 25
#define CONV_NTILE 69       // ceil(17424/256)
#define A_ST 28672          // 112 k-rows * 256 B
#define B_ST 57344          // 112 k-rows * 512 B
#define CSTG (A_ST + B_ST)  // 86016
#define CONV_SMEM (2*CSTG)  // 172032

// xw HMMA geometry: split-K 7, 39 chunks of 64 (273 CTAs = 1 wave)
#define XW_SPLITK 7
#define XW_SMEM 65536

// prep1 fused-launch block ranges
#define CVT_BLOCKS 16398
#define WIH_BLOCKS 3267     // 384*17424/8/256
#define C21_BLOCKS 40

// ---------------- scratch ----------------
__device__ float g_W21[100*100*20];
__device__ float g_W321p[4*100*2800];
__device__ float g_beff[100];
__device__ __align__(16) __half g_xh [(size_t)BATCH*100*PLANE + 1024];
__device__ __align__(16) __half g_xh4[(size_t)BATCH*100*PLANE + 1024];
__device__ __align__(16) __half g_wihh[(size_t)384*FEAT];
__device__ __align__(16) __half g_Aimg[(size_t)NCH_CHUNK*A_ST/2];
__device__ __align__(16) __half g_c3h[(size_t)BATCH*TT*FEAT];
__device__ float g_xwp[(size_t)XW_SPLITK*1600*384];

// ---------------- async-copy helpers ----------------
__device__ __forceinline__ void cp16(void* s, const void* g) {
    unsigned sa = (unsigned)__cvta_generic_to_shared(s);
    asm volatile("cp.async.ca.shared.global [%0], [%1], 16;" :: "r"(sa), "l"(g));
}
__device__ __forceinline__ void cp16z(void* s, const void* g, unsigned sz) {
    unsigned sa = (unsigned)__cvta_generic_to_shared(s);
    asm volatile("cp.async.ca.shared.global [%0], [%1], 16, %2;" :: "r"(sa), "l"(g), "r"(sz));
}

// ---------------- HMMA helpers ----------------
__device__ __forceinline__ void ldsm_x4(uint32_t& r0, uint32_t& r1, uint32_t& r2, uint32_t& r3,
                                        uint32_t addr) {
    asm volatile("ldmatrix.sync.aligned.m8n8.x4.shared.b16 {%0,%1,%2,%3}, [%4];"
                 : "=r"(r0), "=r"(r1), "=r"(r2), "=r"(r3) : "r"(addr));
}
__device__ __forceinline__ void ldsm_x4t(uint32_t& r0, uint32_t& r1, uint32_t& r2, uint32_t& r3,
                                         uint32_t addr) {
    asm volatile("ldmatrix.sync.aligned.m8n8.x4.trans.shared.b16 {%0,%1,%2,%3}, [%4];"
                 : "=r"(r0), "=r"(r1), "=r"(r2), "=r"(r3) : "r"(addr));
}
__device__ __forceinline__ void mma16816(float* c, uint32_t a0, uint32_t a1, uint32_t a2,
                                         uint32_t a3, uint32_t b0, uint32_t b1) {
    asm volatile(
        "mma.sync.aligned.m16n8k16.row.col.f32.f16.f16.f32 "
        "{%0,%1,%2,%3}, {%4,%5,%6,%7}, {%8,%9}, {%0,%1,%2,%3};"
        : "+f"(c[0]), "+f"(c[1]), "+f"(c[2]), "+f"(c[3])
        : "r"(a0), "r"(a1), "r"(a2), "r"(a3), "r"(b0), "r"(b1));
}

// ================= Launch 1: fused cvt_x(+shift) + cvt_wih + compose21 + fold_bias =================
__global__ __launch_bounds__(256)
void prep1(const float* __restrict__ x, __half* __restrict__ xh, __half* __restrict__ xh4,
           const float* __restrict__ wih, __half* __restrict__ wihh,
           const float* __restrict__ w1, const float* __restrict__ w2,
           const float* __restrict__ w3,
           const float* __restrict__ bc1, const float* __restrict__ bc2,
           const float* __restrict__ bc3,
           float* __restrict__ W21, float* __restrict__ beff) {
    const int blk = blockIdx.x;
    if (blk < CVT_BLOCKS) {
        const size_t N = (size_t)BATCH * 100 * PLANE;
        size_t idx = ((size_t)blk * 256 + threadIdx.x) * 8;
        if (idx >= N + 1024) return;
        uint4 out0, out4;
        if (idx < N) {
            float4 a = *(const float4*)(x + idx);
            float4 b = *(const float4*)(x + idx + 4);
            __half2 h0 = __floats2half2_rn(a.x, a.y);
            __half2 h1 = __floats2half2_rn(a.z, a.w);
            __half2 h2 = __floats2half2_rn(b.x, b.y);
            __half2 h3 = __floats2half2_rn(b.z, b.w);
            out0.x = *(uint32_t*)&h0; out0.y = *(uint32_t*)&h1;
            out0.z = *(uint32_t*)&h2; out0.w = *(uint32_t*)&h3;
            if (idx + 12 <= N) {
                float4 c = *(const float4*)(x + idx + 8);
                __half2 g0 = __floats2half2_rn(b.x, b.y);
                __half2 g1 = __floats2half2_rn(b.z, b.w);
                __half2 g2 = __floats2half2_rn(c.x, c.y);
                __half2 g3 = __floats2half2_rn(c.z, c.w);
                out4.x = *(uint32_t*)&g0; out4.y = *(uint32_t*)&g1;
                out4.z = *(uint32_t*)&g2; out4.w = *(uint32_t*)&g3;
            } else {
                float v[8];
#pragma unroll
                for (int j = 0; j < 8; ++j)
                    v[j] = (idx + 4 + j < N) ? x[idx + 4 + j] : 0.f;
                __half2 g0 = __floats2half2_rn(v[0], v[1]);
                __half2 g1 = __floats2half2_rn(v[2], v[3]);
                __half2 g2 = __floats2half2_rn(v[4], v[5]);
                __half2 g3 = __floats2half2_rn(v[6], v[7]);
                out4.x = *(uint32_t*)&g0; out4.y = *(uint32_t*)&g1;
                out4.z = *(uint32_t*)&g2; out4.w = *(uint32_t*)&g3;
            }
        } else {
            out0 = make_uint4(0, 0, 0, 0);
            out4 = make_uint4(0, 0, 0, 0);
        }
        *(uint4*)(xh + idx) = out0;
        *(uint4*)(xh4 + idx) = out4;
    } else if (blk < CVT_BLOCKS + WIH_BLOCKS) {
        size_t idx = ((size_t)(blk - CVT_BLOCKS) * 256 + threadIdx.x) * 8;
        if (idx >= (size_t)384 * FEAT) return;
        int g = (int)(idx / FEAT);
        uint4 out;
        if (g < 300) {
            float4 a = *(const float4*)(wih + idx);
            float4 b = *(const float4*)(wih + idx + 4);
            __half2 h0 = __floats2half2_rn(a.x, a.y);
            __half2 h1 = __floats2half2_rn(a.z, a.w);
            __half2 h2 = __floats2half2_rn(b.x, b.y);
            __half2 h3 = __floats2half2_rn(b.z, b.w);
            out.x = *(uint32_t*)&h0; out.y = *(uint32_t*)&h1;
            out.z = *(uint32_t*)&h2; out.w = *(uint32_t*)&h3;
        } else {
            out = make_uint4(0, 0, 0, 0);
        }
        *(uint4*)(wihh + idx) = out;
    } else if (blk < CVT_BLOCKS + WIH_BLOCKS + C21_BLOCKS) {
        int idx = (blk - CVT_BLOCKS - WIH_BLOCKS) * 256 + threadIdx.x;
        if (idx >= 10000) return;
        int m = idx / 100, i = idx - m * 100;
        float acc[19];
#pragma unroll
        for (int k = 0; k < 19; ++k) acc[k] = 0.f;
        for (int j = 0; j < 100; ++j) {
            float a[10], b[10];
            const float* pa = w2 + (m * 100 + j) * 10;
            const float* pb = w1 + (j * 100 + i) * 10;
#pragma unroll
            for (int k = 0; k < 5; ++k) {
                float2 va = *(const float2*)(pa + 2 * k);
                float2 vb = *(const float2*)(pb + 2 * k);
                a[2 * k] = va.x; a[2 * k + 1] = va.y;
                b[2 * k] = vb.x; b[2 * k + 1] = vb.y;
            }
#pragma unroll
            for (int k2 = 0; k2 < 10; ++k2)
#pragma unroll
                for (int k1 = 0; k1 < 10; ++k1)
                    acc[k2 + k1] += a[k2] * b[k1];
        }
        float* out = W21 + idx * 20;
#pragma unroll
        for (int k = 0; k < 19; ++k) out[k] = acc[k];
        out[19] = 0.f;
    } else {
        __shared__ float b21s[100];
        int o = threadIdx.x;
        if (o < 100) {
            float s = bc2[o];
            for (int i = 0; i < 100; ++i) {
                const float* wr = w2 + o * 1000 + i * 10;
                float t = 0.f;
#pragma unroll
                for (int k = 0; k < 10; ++k) t += wr[k];
                s += t * bc1[i];
            }
            b21s[o] = s;
        }
        __syncthreads();
        if (o < 100) {
            float s = bc3[o];
            for (int i = 0; i < 100; ++i) {
                const float* wr = w3 + o * 1000 + i * 10;
                float t = 0.f;
#pragma unroll
                for (int k = 0; k < 10; ++k) t += wr[k];
                s += t * b21s[i];
            }
            beff[o] = s;
        }
    }
}

// ================= Launch 2: compose321 (4-way j-split, partials) =================
__global__ void compose321_sk(const float* __restrict__ w3, const float* __restrict__ W21,
                              float* __restrict__ W321p) {
    int idx = blockIdx.x * 128 + threadIdx.x;
    if (idx >= 40000) return;
    int jc = idx / 10000;
    int r = idx - jc * 10000;
    int m = r / 100, i = r - m * 100;
    float acc[28];
#pragma unroll
    for (int k = 0; k < 28; ++k) acc[k] = 0.f;
    for (int j = jc * 25; j < jc * 25 + 25; ++j) {
        float a[10], b[20];
        const float* pa = w3 + (m * 100 + j) * 10;
        const float* pb = W21 + (j * 100 + i) * 20;
#pragma unroll
        for (int k = 0; k < 5; ++k) {
            float2 va = *(const float2*)(pa + 2 * k);
            a[2 * k] = va.x; a[2 * k + 1] = va.y;
        }
#pragma unroll
        for (int k = 0; k < 5; ++k) {
            float4 vb = *(const float4*)(pb + 4 * k);
            b[4 * k] = vb.x; b[4 * k + 1] = vb.y; b[4 * k + 2] = vb.z; b[4 * k + 3] = vb.w;
        }
#pragma unroll
        for (int k3 = 0; k3 < 10; ++k3)
#pragma unroll
            for (int k1 = 0; k1 < 19; ++k1)
                acc[k3 + k1] += a[k3] * b[k1];
    }
    float* out = W321p + jc * 280000 + m * 2800 + i * 28;
#pragma unroll
    for (int k = 0; k < 28; ++k) out[k] = acc[k];
}

// ================= Launch 3: prep_A with partial-reduce folded in =================
__global__ void prep_A_red(const float* __restrict__ W321p, __half* __restrict__ Aimg) {
    int idx = blockIdx.x * 256 + threadIdx.x;
    if (idx >= NCH_CHUNK * 112 * 128) return;
    int c = idx / (112 * 128);
    int r2 = idx - c * (112 * 128);
    int m = r2 >> 7, ks = r2 & 127;
    float wv = 0.f;
    if (ks < 112 && m < 100) {
        int off = m * 2800 + c * 112 + ks;
        wv = W321p[off] + W321p[280000 + off] + W321p[560000 + off] + W321p[840000 + off];
    }
    int kb = ks * 2;
    int byte = c * A_ST + m * 256 + (((kb >> 4) ^ (m & 7)) << 4) + (kb & 15);
    Aimg[byte >> 1] = __float2half_rn(wv);
}

// ================= Launch 4: conv via HMMA — one 512-thread CTA, 16 warps 4(m)x4(n:64) =================
__global__ __launch_bounds__(512, 1)
void conv_hmma(const __half* __restrict__ xh, const __half* __restrict__ xh4,
               const __half* __restrict__ Aimg,
               const float* __restrict__ beff, __half* __restrict__ c3h) {
    extern __shared__ __align__(1024) char dsm[];
    const int bb = blockIdx.y;
    const int n0 = blockIdx.x * 256;
    const int tid = threadIdx.x;
    const int wid = tid >> 5, lane = tid & 31;
    const int mg = wid & 3;              // m-group: 32/32/32/16 rows
    const int ngr = wid >> 2;            // n-group: 0..3 (64 each)
    const int m0w = mg * 32;
    const int n0w = ngr * 64;
    const int nfm = (mg == 3) ? 1 : 2;
    const uint32_t dynb = (uint32_t)__cvta_generic_to_shared(dsm);

    float acc[2][8][4];
#pragma unroll
    for (int a = 0; a < 2; ++a)
#pragma unroll
        for (int b = 0; b < 8; ++b)
#pragma unroll
            for (int q = 0; q < 4; ++q) acc[a][b][q] = 0.f;

    const __half* xb  = xh  + (size_t)bb * 100 * PLANE;
    const __half* xb4 = xh4 + (size_t)bb * 100 * PLANE;

    // staging: A 1792 cp16, B 3584 cp16 (512B rows), all cp16 via xh/xh4 parity trick
#define CSTAGE(CC, SS) do {                                                    \
    const __half* asrc = Aimg + (size_t)(CC) * (A_ST / 2);                     \
    char* ad = dsm + (SS) * CSTG;                                              \
    for (int q = tid; q < 1792; q += 512) cp16(ad + q * 16, asrc + q * 8);     \
    char* bd = dsm + (SS) * CSTG + A_ST;                                       \
    int c4 = (CC) * 4;                                                         \
    for (int q = tid; q < 3584; q += 512) {                                    \
        int r = q >> 5, j = q & 31;                                            \
        int chq = r / 28, tap = r - chq * 28;                                  \
        size_t base = (size_t)(c4 + chq) * PLANE + n0 + 132 * tap + j * 8;     \
        const __half* src = ((chq + tap) & 1) ? (xb4 + base - 4) : (xb + base);\
        char* dst = bd + r * 512 + ((j ^ (r & 7)) << 4);                       \
        cp16(dst, src);                                                        \
    }                                                                          \
} while (0)

    CSTAGE(0, 0);
    asm volatile("cp.async.commit_group;" ::: "memory");

    for (int c = 0; c < NCH_CHUNK; ++c) {
        const int s = c & 1;
        if (c + 1 < NCH_CHUNK) {
            CSTAGE(c + 1, 1 - s);
            asm volatile("cp.async.commit_group;" ::: "memory");
            asm volatile("cp.async.wait_group 1;" ::: "memory");
        } else {
            asm volatile("cp.async.wait_group 0;" ::: "memory");
        }
        __syncthreads();

        const uint32_t Ab = dynb + s * CSTG;
        const uint32_t Bb = Ab + A_ST;
#pragma unroll
        for (int kf = 0; kf < 7; ++kf) {
            const int k0 = kf * 16;
            uint32_t a[2][4];
#pragma unroll
            for (int fm = 0; fm < 2; ++fm) {
                if (fm < nfm) {
                    int mrow = m0w + fm * 16 + (lane & 7) + ((lane >> 3) & 1) * 8;
                    int grp = (k0 >> 3) + (lane >> 4);
                    ldsm_x4(a[fm][0], a[fm][1], a[fm][2], a[fm][3],
                            Ab + mrow * 256 + ((grp ^ (mrow & 7)) << 4));
                }
            }
            const int krow = k0 + (lane & 7) + ((lane >> 3) & 1) * 8;
            const uint32_t brow = Bb + krow * 512;
            const int ksw = krow & 7;
            uint32_t b[8][2];
#pragma unroll
            for (int p = 0; p < 4; ++p) {
                int ngi = (n0w >> 3) + p * 2 + (lane >> 4);
                ldsm_x4t(b[p * 2][0], b[p * 2][1], b[p * 2 + 1][0], b[p * 2 + 1][1],
                         brow + ((ngi ^ ksw) << 4));
            }
#pragma unroll
            for (int fm = 0; fm < 2; ++fm) {
                if (fm < nfm) {
#pragma unroll
                    for (int fn = 0; fn < 8; ++fn)
                        mma16816(acc[fm][fn], a[fm][0], a[fm][1], a[fm][2], a[fm][3],
                                 b[fn][0], b[fn][1]);
                }
            }
        }
        __syncthreads();
    }

    // epilogue: bias + fp16 store
#pragma unroll
    for (int fm = 0; fm < 2; ++fm) {
        if (fm >= nfm) continue;
        int mlo = m0w + fm * 16 + (lane >> 2);
        int mhi = mlo + 8;
        float blo = (mlo < 100) ? beff[mlo] : 0.f;
        float bhi = (mhi < 100) ? beff[mhi] : 0.f;
#pragma unroll
        for (int fn = 0; fn < 8; ++fn) {
            int n = n0 + n0w + fn * 8 + 2 * (lane & 3);
            if (n >= FEAT) continue;
            if (mlo < 100) {
                __half2 v = __floats2half2_rn(acc[fm][fn][0] + blo, acc[fm][fn][1] + blo);
                *(__half2*)(c3h + ((size_t)bb * 100 + mlo) * FEAT + n) = v;
            }
            if (mhi < 100) {
                __half2 v = __floats2half2_rn(acc[fm][fn][2] + bhi, acc[fm][fn][3] + bhi);
                *(__half2*)(c3h + ((size_t)bb * 100 + mhi) * FEAT + n) = v;
            }
        }
    }
#undef CSTAGE
}

// ================= Launch 5: GRU input GEMM via HMMA, split-K=7 =================
__global__ __launch_bounds__(256, 2)
void gemm_xw_hmma(const __half* __restrict__ gi, const __half* __restrict__ wihh,
                  float* __restrict__ xwp) {
    extern __shared__ __align__(1024) char dsm[];
    const int bt0 = blockIdx.x * 128;
    const int g0  = blockIdx.y * 128;
    const int z   = blockIdx.z;
    const int kc0 = z * 2496;
    const int nch = 39;
    const int tid = threadIdx.x;
    const int wid = tid >> 5, lane = tid & 31;
    const int m0w = (wid & 3) * 32;
    const int n0w = (wid >> 2) * 64;
    const uint32_t dynb = (uint32_t)__cvta_generic_to_shared(dsm);

    float acc[2][8][4];
#pragma unroll
    for (int a = 0; a < 2; ++a)
#pragma unroll
        for (int b = 0; b < 8; ++b)
#pragma unroll
            for (int q = 0; q < 4; ++q) acc[a][b][q] = 0.f;

#define XSTAGE(KC, SS) do {                                                    \
    for (int q = tid; q < 2048; q += 256) {                                    \
        int isB = q >> 10;                                                     \
        int r = (q >> 3) & 127, j = q & 7;                                     \
        int kg = (KC) + j * 8;                                                 \
        const __half* src;                                                     \
        if (!isB) {                                                            \
            int bt = bt0 + r; if (bt > 1599) bt = 1599;                        \
            src = gi + (size_t)bt * FEAT + kg;                                 \
        } else {                                                               \
            src = wihh + (size_t)(g0 + r) * FEAT + kg;                         \
        }                                                                      \
        unsigned sz = (kg < FEAT) ? 16u : 0u;                                  \
        if (!sz) src = gi;                                                     \
        char* dst = dsm + (SS) * 32768 + isB * 16384 + r * 128 +               \
                    ((j ^ (r & 7)) << 4);                                      \
        cp16z(dst, src, sz);                                                   \
    }                                                                          \
} while (0)

    XSTAGE(kc0, 0);
    asm volatile("cp.async.commit_group;" ::: "memory");

    for (int c = 0; c < nch; ++c) {
        const int s = c & 1;
        if (c + 1 < nch) {
            XSTAGE(kc0 + (c + 1) * 64, 1 - s);
            asm volatile("cp.async.commit_group;" ::: "memory");
            asm volatile("cp.async.wait_group 1;" ::: "memory");
        } else {
            asm volatile("cp.async.wait_group 0;" ::: "memory");
        }
        __syncthreads();

        const uint32_t Ab = dynb + s * 32768;
        const uint32_t Bb = Ab + 16384;
#pragma unroll
        for (int kf = 0; kf < 4; ++kf) {
            const int k0 = kf * 16;
            uint32_t a[2][4];
#pragma unroll
            for (int fm = 0; fm < 2; ++fm) {
                int mrow = m0w + fm * 16 + (lane & 7) + ((lane >> 3) & 1) * 8;
                int grp = (k0 >> 3) + (lane >> 4);
                ldsm_x4(a[fm][0], a[fm][1], a[fm][2], a[fm][3],
                        Ab + mrow * 128 + (((grp ^ (mrow & 7)) & 7) << 4));
            }
            uint32_t b[8][2];
#pragma unroll
            for (int p = 0; p < 4; ++p) {
                int nrow = n0w + p * 16 + ((lane >> 4) & 1) * 8 + (lane & 7);
                int grp = (k0 >> 3) + ((lane >> 3) & 1);
                ldsm_x4(b[p * 2][0], b[p * 2][1], b[p * 2 + 1][0], b[p * 2 + 1][1],
                        Bb + nrow * 128 + (((grp ^ (nrow & 7)) & 7) << 4));
            }
#pragma unroll
            for (int fm = 0; fm < 2; ++fm)
#pragma unroll
                for (int fn = 0; fn < 8; ++fn)
                    mma16816(acc[fm][fn], a[fm][0], a[fm][1], a[fm][2], a[fm][3],
                             b[fn][0], b[fn][1]);
        }
        __syncthreads();
    }

    float* outz = xwp + (size_t)z * 1600 * 384;
#pragma unroll
    for (int fm = 0; fm < 2; ++fm) {
        int mlo = bt0 + m0w + fm * 16 + (lane >> 2);
        int mhi = mlo + 8;
#pragma unroll
        for (int fn = 0; fn < 8; ++fn) {
            int n = g0 + n0w + fn * 8 + 2 * (lane & 3);
            if (mlo < 1600)
                *(float2*)(outz + (size_t)mlo * 384 + n) =
                    make_float2(acc[fm][fn][0], acc[fm][fn][1]);
            if (mhi < 1600)
                *(float2*)(outz + (size_t)mhi * 384 + n) =
                    make_float2(acc[fm][fn][2], acc[fm][fn][3]);
        }
    }
#undef XSTAGE
}

// ================= Launch 6: GRU + heads, split-K reduce fused =================
__global__ __launch_bounds__(320, 1)
void gru_kernel(const float* __restrict__ xwp, const float* __restrict__ bih,
                const float* __restrict__ whh, const float* __restrict__ bhh,
                const float* __restrict__ wy1, const float* __restrict__ by1,
                const float* __restrict__ wy2, const float* __restrict__ by2,
                float* __restrict__ out) {
    const int b = blockIdx.x;
    const int tid = threadIdx.x;
    __shared__ float h_s[HID];
    __shared__ float gh_s[3 * HID];
    __shared__ float xw_s[2][3 * HID];
    __shared__ float wy_s[(NC + NL) * HID];
    __shared__ float by_s[NC + NL];

    for (int j = tid; j < NC * HID; j += 320) wy_s[j] = wy1[j];
    for (int j = tid; j < NL * HID; j += 320) wy_s[NC * HID + j] = wy2[j];
    if (tid < NC) by_s[tid] = by1[tid];
    else if (tid < NC + NL) by_s[tid] = by2[tid - NC];
    if (tid < HID) h_s[tid] = 0.f;

    float wreg[HID];
    float bh = 0.f, bxw = 0.f;
    if (tid < 3 * HID) {
        const float4* wrow = (const float4*)(whh + (size_t)tid * HID);
#pragma unroll
        for (int j = 0; j < HID / 4; ++j) {
            float4 v = wrow[j];
            wreg[4 * j] = v.x; wreg[4 * j + 1] = v.y;
            wreg[4 * j + 2] = v.z; wreg[4 * j + 3] = v.w;
        }
        bh = bhh[tid];
        bxw = bih[tid];
        const float* base = xwp + (size_t)(b * TT + 0) * 384 + tid;
        float s = bxw;
#pragma unroll
        for (int p = 0; p < XW_SPLITK; ++p) s += base[(size_t)p * 1600 * 384];
        xw_s[0][tid] = s;
    }
    __syncthreads();

    float* y1o = out + (size_t)b * TT * NC;
    float* y2o = out + (size_t)BATCH * TT * NC + (size_t)b * TT * NL;

    for (int t = 0; t < TT; ++t) {
        float pf[XW_SPLITK];
        if (tid < 3 * HID) {
            float s0 = 0.f, s1 = 0.f, s2 = 0.f, s3 = 0.f;
#pragma unroll
            for (int j = 0; j < HID; j += 4) {
                s0 += wreg[j]     * h_s[j];
                s1 += wreg[j + 1] * h_s[j + 1];
                s2 += wreg[j + 2] * h_s[j + 2];
                s3 += wreg[j + 3] * h_s[j + 3];
            }
            gh_s[tid] = bh + ((s0 + s1) + (s2 + s3));
            if (t + 1 < TT) {
                const float* base = xwp + (size_t)(b * TT + t + 1) * 384 + tid;
#pragma unroll
                for (int p = 0; p < XW_SPLITK; ++p) pf[p] = base[(size_t)p * 1600 * 384];
            }
        } else if (t > 0 && tid < 300 + NC + NL) {
            int c = tid - 300;
            float s = by_s[c];
            const float* wr = &wy_s[c * HID];
#pragma unroll 4
            for (int j = 0; j < HID; ++j) s += wr[j] * h_s[j];
            if (c < NC) y1o[(t - 1) * NC + c] = 1.f / (1.f + expf(-s));
            else        y2o[(t - 1) * NL + (c - NC)] = tanhf(s) * 10.f;
        }
        __syncthreads();
        if (tid < HID) {
            const float* xwt = xw_s[t & 1];
            float ghr = gh_s[tid], ghz = gh_s[HID + tid], ghn = gh_s[2 * HID + tid];
            float xr = xwt[tid], xz = xwt[HID + tid], xn = xwt[2 * HID + tid];
            float r = 1.f / (1.f + expf(-(xr + ghr)));
            float z = 1.f / (1.f + expf(-(xz + ghz)));
            float n = tanhf(xn + r * ghn);
            h_s[tid] = (1.f - z) * n + z * h_s[tid];
        }
        if (tid < 3 * HID && t + 1 < TT) {
            float s = bxw;
#pragma unroll
            for (int p = 0; p < XW_SPLITK; ++p) s += pf[p];
            xw_s[(t + 1) & 1][tid] = s;
        }
        __syncthreads();
    }
    if (tid >= 300 && tid < 300 + NC + NL) {
        int c = tid - 300;
        float s = by_s[c];
        const float* wr = &wy_s[c * HID];
#pragma unroll 4
        for (int j = 0; j < HID; ++j) s += wr[j] * h_s[j];
        if (c < NC) y1o[(TT - 1) * NC + c] = 1.f / (1.f + expf(-s));
        else        y2o[(TT - 1) * NL + (c - NC)] = tanhf(s) * 10.f;
    }
}

// ---------------- launch ----------------
extern "C" void kernel_launch(void* const* d_in, const int* in_sizes, int n_in,
                              void* d_out, int out_size) {
    const float* x    = (const float*)d_in[0];
    const float* w1   = (const float*)d_in[1];
    const float* bc1  = (const float*)d_in[2];
    const float* w2   = (const float*)d_in[3];
    const float* bc2  = (const float*)d_in[4];
    const float* w3   = (const float*)d_in[5];
    const float* bc3  = (const float*)d_in[6];
    const float* w_ih = (const float*)d_in[7];
    const float* w_hh = (const float*)d_in[8];
    const float* b_ih = (const float*)d_in[9];
    const float* b_hh = (const float*)d_in[10];
    const float* w_y1 = (const float*)d_in[11];
    const float* b_y1 = (const float*)d_in[12];
    const float* w_y2 = (const float*)d_in[13];
    const float* b_y2 = (const float*)d_in[14];

    float *W21, *W321p, *beff, *xwp;
    __half *xh, *xh4, *wihh, *Aimg, *c3h;
    cudaGetSymbolAddress((void**)&W21,   g_W21);
    cudaGetSymbolAddress((void**)&W321p, g_W321p);
    cudaGetSymbolAddress((void**)&beff,  g_beff);
    cudaGetSymbolAddress((void**)&xwp,   g_xwp);
    cudaGetSymbolAddress((void**)&xh,    g_xh);
    cudaGetSymbolAddress((void**)&xh4,   g_xh4);
    cudaGetSymbolAddress((void**)&wihh,  g_wihh);
    cudaGetSymbolAddress((void**)&Aimg,  g_Aimg);
    cudaGetSymbolAddress((void**)&c3h,   g_c3h);

    cudaFuncSetAttribute(conv_hmma, cudaFuncAttributeMaxDynamicSharedMemorySize, CONV_SMEM);
    cudaFuncSetAttribute(gemm_xw_hmma, cudaFuncAttributeMaxDynamicSharedMemorySize, XW_SMEM);

    // L1: cvt_x (+ shifted copy) + cvt_wih + compose21 + fold_bias (fused)
    prep1<<<CVT_BLOCKS + WIH_BLOCKS + C21_BLOCKS + 1, 256>>>(
        x, xh, xh4, w_ih, wihh, w1, w2, w3, bc1, bc2, bc3, W21, beff);
    // L2: compose321 partials
    compose321_sk<<<(40000 + 127) / 128, 128>>>(w3, W21, W321p);
    // L3: A-image build + partial reduce
    prep_A_red<<<(NCH_CHUNK * 112 * 128 + 255) / 256, 256>>>(W321p, Aimg);
    // L4: conv (profiled slot), 512-thread CTA, 16 warps 4x4
    conv_hmma<<<dim3(CONV_NTILE, BATCH), 512, CONV_SMEM>>>(xh, xh4, Aimg, beff, c3h);
    // L5: GRU input GEMM (split-K partials)
    gemm_xw_hmma<<<dim3(13, 3, XW_SPLITK), 256, XW_SMEM>>>(c3h, wihh, xwp);
    // L6: GRU + heads with fused split-K reduce
    gru_kernel<<<BATCH, 320>>>(xwp, b_ih, w_hh, b_hh, w_y1, b_y1, w_y2, b_y2, (float*)d_out);
}

// round 17
// speedup vs baseline: 1.1996x; 1.0444x over previous
#include <cuda_runtime.h>
#include <cuda_fp16.h>
#include <cstdint>

// ---------------- problem constants ----------------
#define BATCH 16
#define TT    100
#define W_IN  132
#define H1    159
#define H4    132
#define PLANE (H1*W_IN)     // 20988  (== 4 mod 8)
#define FEAT  (H4*W_IN)     // 17424
#define HID   100
#define NC    14
#define NL    3

// conv HMMA geometry (R13 proven): CTA 112(m) x 128(n), 256 threads, 8 warps 4(m)x2(n), 2 CTAs/SM
#define NCH_CHUNK 25
#define CONV_NTILE 137      // ceil(17424/128)
#define A_ST 28672          // 112 k-rows * 256 B
#define B_ST 28672          // 112 k-rows * 256 B
#define CSTG (A_ST + B_ST)  // 57344
#define CONV_SMEM (2*CSTG)  // 114688  (2 CTAs fit the 228KB carveout)

// xw HMMA geometry: split-K 7, 39 chunks of 64 (273 CTAs = 1 wave)
#define XW_SPLITK 7
#define XW_SMEM 65536

// prep1 fused-launch block ranges
#define CVT_BLOCKS 16398
#define WIH_BLOCKS 3267     // 384*17424/8/256
#define C21_BLOCKS 40

// ---------------- scratch ----------------
__device__ float g_W21[100*100*20];
__device__ float g_W321p[4*100*2800];
__device__ float g_beff[100];
__device__ __align__(16) __half g_xh [(size_t)BATCH*100*PLANE + 1024];
__device__ __align__(16) __half g_xh4[(size_t)BATCH*100*PLANE + 1024];
__device__ __align__(16) __half g_wihh[(size_t)384*FEAT];
__device__ __align__(16) __half g_Aimg[(size_t)NCH_CHUNK*A_ST/2];
__device__ __align__(16) __half g_c3h[(size_t)BATCH*TT*FEAT];
__device__ float g_xwp[(size_t)XW_SPLITK*1600*384];

// ---------------- async-copy helpers ----------------
__device__ __forceinline__ void cp16(void* s, const void* g) {
    unsigned sa = (unsigned)__cvta_generic_to_shared(s);
    asm volatile("cp.async.ca.shared.global [%0], [%1], 16;" :: "r"(sa), "l"(g));
}
__device__ __forceinline__ void cp16z(void* s, const void* g, unsigned sz) {
    unsigned sa = (unsigned)__cvta_generic_to_shared(s);
    asm volatile("cp.async.ca.shared.global [%0], [%1], 16, %2;" :: "r"(sa), "l"(g), "r"(sz));
}

// ---------------- HMMA helpers ----------------
__device__ __forceinline__ void ldsm_x4(uint32_t& r0, uint32_t& r1, uint32_t& r2, uint32_t& r3,
                                        uint32_t addr) {
    asm volatile("ldmatrix.sync.aligned.m8n8.x4.shared.b16 {%0,%1,%2,%3}, [%4];"
                 : "=r"(r0), "=r"(r1), "=r"(r2), "=r"(r3) : "r"(addr));
}
__device__ __forceinline__ void ldsm_x4t(uint32_t& r0, uint32_t& r1, uint32_t& r2, uint32_t& r3,
                                         uint32_t addr) {
    asm volatile("ldmatrix.sync.aligned.m8n8.x4.trans.shared.b16 {%0,%1,%2,%3}, [%4];"
                 : "=r"(r0), "=r"(r1), "=r"(r2), "=r"(r3) : "r"(addr));
}
__device__ __forceinline__ void mma16816(float* c, uint32_t a0, uint32_t a1, uint32_t a2,
                                         uint32_t a3, uint32_t b0, uint32_t b1) {
    asm volatile(
        "mma.sync.aligned.m16n8k16.row.col.f32.f16.f16.f32 "
        "{%0,%1,%2,%3}, {%4,%5,%6,%7}, {%8,%9}, {%0,%1,%2,%3};"
        : "+f"(c[0]), "+f"(c[1]), "+f"(c[2]), "+f"(c[3])
        : "r"(a0), "r"(a1), "r"(a2), "r"(a3), "r"(b0), "r"(b1));
}

// ================= Launch 1: fused cvt_x(+shift) + cvt_wih + compose21 + fold_bias =================
__global__ __launch_bounds__(256)
void prep1(const float* __restrict__ x, __half* __restrict__ xh, __half* __restrict__ xh4,
           const float* __restrict__ wih, __half* __restrict__ wihh,
           const float* __restrict__ w1, const float* __restrict__ w2,
           const float* __restrict__ w3,
           const float* __restrict__ bc1, const float* __restrict__ bc2,
           const float* __restrict__ bc3,
           float* __restrict__ W21, float* __restrict__ beff) {
    const int blk = blockIdx.x;
    if (blk < CVT_BLOCKS) {
        const size_t N = (size_t)BATCH * 100 * PLANE;
        size_t idx = ((size_t)blk * 256 + threadIdx.x) * 8;
        if (idx >= N + 1024) return;
        uint4 out0, out4;
        if (idx < N) {
            float4 a = *(const float4*)(x + idx);
            float4 b = *(const float4*)(x + idx + 4);
            __half2 h0 = __floats2half2_rn(a.x, a.y);
            __half2 h1 = __floats2half2_rn(a.z, a.w);
            __half2 h2 = __floats2half2_rn(b.x, b.y);
            __half2 h3 = __floats2half2_rn(b.z, b.w);
            out0.x = *(uint32_t*)&h0; out0.y = *(uint32_t*)&h1;
            out0.z = *(uint32_t*)&h2; out0.w = *(uint32_t*)&h3;
            if (idx + 12 <= N) {
                float4 c = *(const float4*)(x + idx + 8);
                __half2 g0 = __floats2half2_rn(b.x, b.y);
                __half2 g1 = __floats2half2_rn(b.z, b.w);
                __half2 g2 = __floats2half2_rn(c.x, c.y);
                __half2 g3 = __floats2half2_rn(c.z, c.w);
                out4.x = *(uint32_t*)&g0; out4.y = *(uint32_t*)&g1;
                out4.z = *(uint32_t*)&g2; out4.w = *(uint32_t*)&g3;
            } else {
                float v[8];
#pragma unroll
                for (int j = 0; j < 8; ++j)
                    v[j] = (idx + 4 + j < N) ? x[idx + 4 + j] : 0.f;
                __half2 g0 = __floats2half2_rn(v[0], v[1]);
                __half2 g1 = __floats2half2_rn(v[2], v[3]);
                __half2 g2 = __floats2half2_rn(v[4], v[5]);
                __half2 g3 = __floats2half2_rn(v[6], v[7]);
                out4.x = *(uint32_t*)&g0; out4.y = *(uint32_t*)&g1;
                out4.z = *(uint32_t*)&g2; out4.w = *(uint32_t*)&g3;
            }
        } else {
            out0 = make_uint4(0, 0, 0, 0);
            out4 = make_uint4(0, 0, 0, 0);
        }
        *(uint4*)(xh + idx) = out0;
        *(uint4*)(xh4 + idx) = out4;
    } else if (blk < CVT_BLOCKS + WIH_BLOCKS) {
        size_t idx = ((size_t)(blk - CVT_BLOCKS) * 256 + threadIdx.x) * 8;
        if (idx >= (size_t)384 * FEAT) return;
        int g = (int)(idx / FEAT);
        uint4 out;
        if (g < 300) {
            float4 a = *(const float4*)(wih + idx);
            float4 b = *(const float4*)(wih + idx + 4);
            __half2 h0 = __floats2half2_rn(a.x, a.y);
            __half2 h1 = __floats2half2_rn(a.z, a.w);
            __half2 h2 = __floats2half2_rn(b.x, b.y);
            __half2 h3 = __floats2half2_rn(b.z, b.w);
            out.x = *(uint32_t*)&h0; out.y = *(uint32_t*)&h1;
            out.z = *(uint32_t*)&h2; out.w = *(uint32_t*)&h3;
        } else {
            out = make_uint4(0, 0, 0, 0);
        }
        *(uint4*)(wihh + idx) = out;
    } else if (blk < CVT_BLOCKS + WIH_BLOCKS + C21_BLOCKS) {
        int idx = (blk - CVT_BLOCKS - WIH_BLOCKS) * 256 + threadIdx.x;
        if (idx >= 10000) return;
        int m = idx / 100, i = idx - m * 100;
        float acc[19];
#pragma unroll
        for (int k = 0; k < 19; ++k) acc[k] = 0.f;
        for (int j = 0; j < 100; ++j) {
            float a[10], b[10];
            const float* pa = w2 + (m * 100 + j) * 10;
            const float* pb = w1 + (j * 100 + i) * 10;
#pragma unroll
            for (int k = 0; k < 5; ++k) {
                float2 va = *(const float2*)(pa + 2 * k);
                float2 vb = *(const float2*)(pb + 2 * k);
                a[2 * k] = va.x; a[2 * k + 1] = va.y;
                b[2 * k] = vb.x; b[2 * k + 1] = vb.y;
            }
#pragma unroll
            for (int k2 = 0; k2 < 10; ++k2)
#pragma unroll
                for (int k1 = 0; k1 < 10; ++k1)
                    acc[k2 + k1] += a[k2] * b[k1];
        }
        float* out = W21 + idx * 20;
#pragma unroll
        for (int k = 0; k < 19; ++k) out[k] = acc[k];
        out[19] = 0.f;
    } else {
        __shared__ float b21s[100];
        int o = threadIdx.x;
        if (o < 100) {
            float s = bc2[o];
            for (int i = 0; i < 100; ++i) {
                const float* wr = w2 + o * 1000 + i * 10;
                float t = 0.f;
#pragma unroll
                for (int k = 0; k < 10; ++k) t += wr[k];
                s += t * bc1[i];
            }
            b21s[o] = s;
        }
        __syncthreads();
        if (o < 100) {
            float s = bc3[o];
            for (int i = 0; i < 100; ++i) {
                const float* wr = w3 + o * 1000 + i * 10;
                float t = 0.f;
#pragma unroll
                for (int k = 0; k < 10; ++k) t += wr[k];
                s += t * b21s[i];
            }
            beff[o] = s;
        }
    }
}

// ================= Launch 2: compose321 (4-way j-split, partials) =================
__global__ void compose321_sk(const float* __restrict__ w3, const float* __restrict__ W21,
                              float* __restrict__ W321p) {
    int idx = blockIdx.x * 128 + threadIdx.x;
    if (idx >= 40000) return;
    int jc = idx / 10000;
    int r = idx - jc * 10000;
    int m = r / 100, i = r - m * 100;
    float acc[28];
#pragma unroll
    for (int k = 0; k < 28; ++k) acc[k] = 0.f;
    for (int j = jc * 25; j < jc * 25 + 25; ++j) {
        float a[10], b[20];
        const float* pa = w3 + (m * 100 + j) * 10;
        const float* pb = W21 + (j * 100 + i) * 20;
#pragma unroll
        for (int k = 0; k < 5; ++k) {
            float2 va = *(const float2*)(pa + 2 * k);
            a[2 * k] = va.x; a[2 * k + 1] = va.y;
        }
#pragma unroll
        for (int k = 0; k < 5; ++k) {
            float4 vb = *(const float4*)(pb + 4 * k);
            b[4 * k] = vb.x; b[4 * k + 1] = vb.y; b[4 * k + 2] = vb.z; b[4 * k + 3] = vb.w;
        }
#pragma unroll
        for (int k3 = 0; k3 < 10; ++k3)
#pragma unroll
            for (int k1 = 0; k1 < 19; ++k1)
                acc[k3 + k1] += a[k3] * b[k1];
    }
    float* out = W321p + jc * 280000 + m * 2800 + i * 28;
#pragma unroll
    for (int k = 0; k < 28; ++k) out[k] = acc[k];
}

// ================= Launch 3: prep_A with partial-reduce folded in =================
__global__ void prep_A_red(const float* __restrict__ W321p, __half* __restrict__ Aimg) {
    int idx = blockIdx.x * 256 + threadIdx.x;
    if (idx >= NCH_CHUNK * 112 * 128) return;
    int c = idx / (112 * 128);
    int r2 = idx - c * (112 * 128);
    int m = r2 >> 7, ks = r2 & 127;
    float wv = 0.f;
    if (ks < 112 && m < 100) {
        int off = m * 2800 + c * 112 + ks;
        wv = W321p[off] + W321p[280000 + off] + W321p[560000 + off] + W321p[840000 + off];
    }
    int kb = ks * 2;
    int byte = c * A_ST + m * 256 + (((kb >> 4) ^ (m & 7)) << 4) + (kb & 15);
    Aimg[byte >> 1] = __float2half_rn(wv);
}

// ================= Launch 4: conv via HMMA (R13 proven: 8 warps 4(m)x2(n), 2 CTAs/SM) =================
__global__ __launch_bounds__(256, 1)
void conv_hmma(const __half* __restrict__ xh, const __half* __restrict__ xh4,
               const __half* __restrict__ Aimg,
               const float* __restrict__ beff, __half* __restrict__ c3h) {
    extern __shared__ __align__(1024) char dsm[];
    const int bb = blockIdx.y;
    const int n0 = blockIdx.x * 128;
    const int tid = threadIdx.x;
    const int wid = tid >> 5, lane = tid & 31;
    const int mg = wid & 3;              // m-group: rows mg*32 (+32, or +16 for mg==3)
    const int ng = wid >> 2;             // n-group: 0 or 1
    const int m0w = mg * 32;
    const int n0w = ng * 64;
    const int nfm = (mg == 3) ? 1 : 2;
    const uint32_t dynb = (uint32_t)__cvta_generic_to_shared(dsm);

    float acc[2][8][4];
#pragma unroll
    for (int a = 0; a < 2; ++a)
#pragma unroll
        for (int b = 0; b < 8; ++b)
#pragma unroll
            for (int q = 0; q < 4; ++q) acc[a][b][q] = 0.f;

    const __half* xb  = xh  + (size_t)bb * 100 * PLANE;
    const __half* xb4 = xh4 + (size_t)bb * 100 * PLANE;

    // staging: A 1792 cp16, B 1792 cp16 (256B rows) via xh/xh4 parity trick
#define CSTAGE(CC, SS) do {                                                    \
    const __half* asrc = Aimg + (size_t)(CC) * (A_ST / 2);                     \
    char* ad = dsm + (SS) * CSTG;                                              \
    for (int q = tid; q < 1792; q += 256) cp16(ad + q * 16, asrc + q * 8);     \
    char* bd = dsm + (SS) * CSTG + A_ST;                                       \
    int c4 = (CC) * 4;                                                         \
    for (int q = tid; q < 1792; q += 256) {                                    \
        int r = q >> 4, j = q & 15;                                            \
        int chq = r / 28, tap = r - chq * 28;                                  \
        size_t base = (size_t)(c4 + chq) * PLANE + n0 + 132 * tap + j * 8;     \
        const __half* src = ((chq + tap) & 1) ? (xb4 + base - 4) : (xb + base);\
        char* dst = bd + r * 256 + ((j ^ (r & 7)) << 4);                       \
        cp16(dst, src);                                                        \
    }                                                                          \
} while (0)

    CSTAGE(0, 0);
    asm volatile("cp.async.commit_group;" ::: "memory");

    for (int c = 0; c < NCH_CHUNK; ++c) {
        const int s = c & 1;
        if (c + 1 < NCH_CHUNK) {
            CSTAGE(c + 1, 1 - s);
            asm volatile("cp.async.commit_group;" ::: "memory");
            asm volatile("cp.async.wait_group 1;" ::: "memory");
        } else {
            asm volatile("cp.async.wait_group 0;" ::: "memory");
        }
        __syncthreads();

        const uint32_t Ab = dynb + s * CSTG;
        const uint32_t Bb = Ab + A_ST;
#pragma unroll
        for (int kf = 0; kf < 7; ++kf) {
            const int k0 = kf * 16;
            uint32_t a[2][4];
#pragma unroll
            for (int fm = 0; fm < 2; ++fm) {
                if (fm < nfm) {
                    int mrow = m0w + fm * 16 + (lane & 7) + ((lane >> 3) & 1) * 8;
                    int grp = (k0 >> 3) + (lane >> 4);
                    ldsm_x4(a[fm][0], a[fm][1], a[fm][2], a[fm][3],
                            Ab + mrow * 256 + ((grp ^ (mrow & 7)) << 4));
                }
            }
            uint32_t b[8][2];
#pragma unroll
            for (int p = 0; p < 4; ++p) {
                int krow = k0 + (lane & 7) + ((lane >> 3) & 1) * 8;
                int ngi = (n0w >> 3) + p * 2 + (lane >> 4);
                ldsm_x4t(b[p * 2][0], b[p * 2][1], b[p * 2 + 1][0], b[p * 2 + 1][1],
                         Bb + krow * 256 + ((ngi ^ (krow & 7)) << 4));
            }
#pragma unroll
            for (int fm = 0; fm < 2; ++fm) {
                if (fm < nfm) {
#pragma unroll
                    for (int fn = 0; fn < 8; ++fn)
                        mma16816(acc[fm][fn], a[fm][0], a[fm][1], a[fm][2], a[fm][3],
                                 b[fn][0], b[fn][1]);
                }
            }
        }
        __syncthreads();
    }

    // epilogue: bias + fp16 store
#pragma unroll
    for (int fm = 0; fm < 2; ++fm) {
        if (fm >= nfm) continue;
        int mlo = m0w + fm * 16 + (lane >> 2);
        int mhi = mlo + 8;
        float blo = (mlo < 100) ? beff[mlo] : 0.f;
        float bhi = (mhi < 100) ? beff[mhi] : 0.f;
#pragma unroll
        for (int fn = 0; fn < 8; ++fn) {
            int n = n0 + n0w + fn * 8 + 2 * (lane & 3);
            if (n >= FEAT) continue;
            if (mlo < 100) {
                __half2 v = __floats2half2_rn(acc[fm][fn][0] + blo, acc[fm][fn][1] + blo);
                *(__half2*)(c3h + ((size_t)bb * 100 + mlo) * FEAT + n) = v;
            }
            if (mhi < 100) {
                __half2 v = __floats2half2_rn(acc[fm][fn][2] + bhi, acc[fm][fn][3] + bhi);
                *(__half2*)(c3h + ((size_t)bb * 100 + mhi) * FEAT + n) = v;
            }
        }
    }
#undef CSTAGE
}

// ================= Launch 5: GRU input GEMM via HMMA, split-K=7 =================
__global__ __launch_bounds__(256, 2)
void gemm_xw_hmma(const __half* __restrict__ gi, const __half* __restrict__ wihh,
                  float* __restrict__ xwp) {
    extern __shared__ __align__(1024) char dsm[];
    const int bt0 = blockIdx.x * 128;
    const int g0  = blockIdx.y * 128;
    const int z   = blockIdx.z;
    const int kc0 = z * 2496;
    const int nch = 39;
    const int tid = threadIdx.x;
    const int wid = tid >> 5, lane = tid & 31;
    const int m0w = (wid & 3) * 32;
    const int n0w = (wid >> 2) * 64;
    const uint32_t dynb = (uint32_t)__cvta_generic_to_shared(dsm);

    float acc[2][8][4];
#pragma unroll
    for (int a = 0; a < 2; ++a)
#pragma unroll
        for (int b = 0; b < 8; ++b)
#pragma unroll
            for (int q = 0; q < 4; ++q) acc[a][b][q] = 0.f;

#define XSTAGE(KC, SS) do {                                                    \
    for (int q = tid; q < 2048; q += 256) {                                    \
        int isB = q >> 10;                                                     \
        int r = (q >> 3) & 127, j = q & 7;                                     \
        int kg = (KC) + j * 8;                                                 \
        const __half* src;                                                     \
        if (!isB) {                                                            \
            int bt = bt0 + r; if (bt > 1599) bt = 1599;                        \
            src = gi + (size_t)bt * FEAT + kg;                                 \
        } else {                                                               \
            src = wihh + (size_t)(g0 + r) * FEAT + kg;                         \
        }                                                                      \
        unsigned sz = (kg < FEAT) ? 16u : 0u;                                  \
        if (!sz) src = gi;                                                     \
        char* dst = dsm + (SS) * 32768 + isB * 16384 + r * 128 +               \
                    ((j ^ (r & 7)) << 4);                                      \
        cp16z(dst, src, sz);                                                   \
    }                                                                          \
} while (0)

    XSTAGE(kc0, 0);
    asm volatile("cp.async.commit_group;" ::: "memory");

    for (int c = 0; c < nch; ++c) {
        const int s = c & 1;
        if (c + 1 < nch) {
            XSTAGE(kc0 + (c + 1) * 64, 1 - s);
            asm volatile("cp.async.commit_group;" ::: "memory");
            asm volatile("cp.async.wait_group 1;" ::: "memory");
        } else {
            asm volatile("cp.async.wait_group 0;" ::: "memory");
        }
        __syncthreads();

        const uint32_t Ab = dynb + s * 32768;
        const uint32_t Bb = Ab + 16384;
#pragma unroll
        for (int kf = 0; kf < 4; ++kf) {
            const int k0 = kf * 16;
            uint32_t a[2][4];
#pragma unroll
            for (int fm = 0; fm < 2; ++fm) {
                int mrow = m0w + fm * 16 + (lane & 7) + ((lane >> 3) & 1) * 8;
                int grp = (k0 >> 3) + (lane >> 4);
                ldsm_x4(a[fm][0], a[fm][1], a[fm][2], a[fm][3],
                        Ab + mrow * 128 + (((grp ^ (mrow & 7)) & 7) << 4));
            }
            uint32_t b[8][2];
#pragma unroll
            for (int p = 0; p < 4; ++p) {
                int nrow = n0w + p * 16 + ((lane >> 4) & 1) * 8 + (lane & 7);
                int grp = (k0 >> 3) + ((lane >> 3) & 1);
                ldsm_x4(b[p * 2][0], b[p * 2][1], b[p * 2 + 1][0], b[p * 2 + 1][1],
                        Bb + nrow * 128 + (((grp ^ (nrow & 7)) & 7) << 4));
            }
#pragma unroll
            for (int fm = 0; fm < 2; ++fm)
#pragma unroll
                for (int fn = 0; fn < 8; ++fn)
                    mma16816(acc[fm][fn], a[fm][0], a[fm][1], a[fm][2], a[fm][3],
                             b[fn][0], b[fn][1]);
        }
        __syncthreads();
    }

    float* outz = xwp + (size_t)z * 1600 * 384;
#pragma unroll
    for (int fm = 0; fm < 2; ++fm) {
        int mlo = bt0 + m0w + fm * 16 + (lane >> 2);
        int mhi = mlo + 8;
#pragma unroll
        for (int fn = 0; fn < 8; ++fn) {
            int n = g0 + n0w + fn * 8 + 2 * (lane & 3);
            if (mlo < 1600)
                *(float2*)(outz + (size_t)mlo * 384 + n) =
                    make_float2(acc[fm][fn][0], acc[fm][fn][1]);
            if (mhi < 1600)
                *(float2*)(outz + (size_t)mhi * 384 + n) =
                    make_float2(acc[fm][fn][2], acc[fm][fn][3]);
        }
    }
#undef XSTAGE
}

// ================= Launch 6: GRU + heads, split-K reduce fused =================
__global__ __launch_bounds__(320, 1)
void gru_kernel(const float* __restrict__ xwp, const float* __restrict__ bih,
                const float* __restrict__ whh, const float* __restrict__ bhh,
                const float* __restrict__ wy1, const float* __restrict__ by1,
                const float* __restrict__ wy2, const float* __restrict__ by2,
                float* __restrict__ out) {
    const int b = blockIdx.x;
    const int tid = threadIdx.x;
    __shared__ float h_s[HID];
    __shared__ float gh_s[3 * HID];
    __shared__ float xw_s[2][3 * HID];
    __shared__ float wy_s[(NC + NL) * HID];
    __shared__ float by_s[NC + NL];

    for (int j = tid; j < NC * HID; j += 320) wy_s[j] = wy1[j];
    for (int j = tid; j < NL * HID; j += 320) wy_s[NC * HID + j] = wy2[j];
    if (tid < NC) by_s[tid] = by1[tid];
    else if (tid < NC + NL) by_s[tid] = by2[tid - NC];
    if (tid < HID) h_s[tid] = 0.f;

    float wreg[HID];
    float bh = 0.f, bxw = 0.f;
    if (tid < 3 * HID) {
        const float4* wrow = (const float4*)(whh + (size_t)tid * HID);
#pragma unroll
        for (int j = 0; j < HID / 4; ++j) {
            float4 v = wrow[j];
            wreg[4 * j] = v.x; wreg[4 * j + 1] = v.y;
            wreg[4 * j + 2] = v.z; wreg[4 * j + 3] = v.w;
        }
        bh = bhh[tid];
        bxw = bih[tid];
        const float* base = xwp + (size_t)(b * TT + 0) * 384 + tid;
        float s = bxw;
#pragma unroll
        for (int p = 0; p < XW_SPLITK; ++p) s += base[(size_t)p * 1600 * 384];
        xw_s[0][tid] = s;
    }
    __syncthreads();

    float* y1o = out + (size_t)b * TT * NC;
    float* y2o = out + (size_t)BATCH * TT * NC + (size_t)b * TT * NL;

    for (int t = 0; t < TT; ++t) {
        float pf[XW_SPLITK];
        if (tid < 3 * HID) {
            float s0 = 0.f, s1 = 0.f, s2 = 0.f, s3 = 0.f;
#pragma unroll
            for (int j = 0; j < HID; j += 4) {
                s0 += wreg[j]     * h_s[j];
                s1 += wreg[j + 1] * h_s[j + 1];
                s2 += wreg[j + 2] * h_s[j + 2];
                s3 += wreg[j + 3] * h_s[j + 3];
            }
            gh_s[tid] = bh + ((s0 + s1) + (s2 + s3));
            if (t + 1 < TT) {
                const float* base = xwp + (size_t)(b * TT + t + 1) * 384 + tid;
#pragma unroll
                for (int p = 0; p < XW_SPLITK; ++p) pf[p] = base[(size_t)p * 1600 * 384];
            }
        } else if (t > 0 && tid < 300 + NC + NL) {
            int c = tid - 300;
            float s = by_s[c];
            const float* wr = &wy_s[c * HID];
#pragma unroll 4
            for (int j = 0; j < HID; ++j) s += wr[j] * h_s[j];
            if (c < NC) y1o[(t - 1) * NC + c] = 1.f / (1.f + expf(-s));
            else        y2o[(t - 1) * NL + (c - NC)] = tanhf(s) * 10.f;
        }
        __syncthreads();
        if (tid < HID) {
            const float* xwt = xw_s[t & 1];
            float ghr = gh_s[tid], ghz = gh_s[HID + tid], ghn = gh_s[2 * HID + tid];
            float xr = xwt[tid], xz = xwt[HID + tid], xn = xwt[2 * HID + tid];
            float r = 1.f / (1.f + expf(-(xr + ghr)));
            float z = 1.f / (1.f + expf(-(xz + ghz)));
            float n = tanhf(xn + r * ghn);
            h_s[tid] = (1.f - z) * n + z * h_s[tid];
        }
        if (tid < 3 * HID && t + 1 < TT) {
            float s = bxw;
#pragma unroll
            for (int p = 0; p < XW_SPLITK; ++p) s += pf[p];
            xw_s[(t + 1) & 1][tid] = s;
        }
        __syncthreads();
    }
    if (tid >= 300 && tid < 300 + NC + NL) {
        int c = tid - 300;
        float s = by_s[c];
        const float* wr = &wy_s[c * HID];
#pragma unroll 4
        for (int j = 0; j < HID; ++j) s += wr[j] * h_s[j];
        if (c < NC) y1o[(TT - 1) * NC + c] = 1.f / (1.f + expf(-s));
        else        y2o[(TT - 1) * NL + (c - NC)] = tanhf(s) * 10.f;
    }
}

// ---------------- launch ----------------
extern "C" void kernel_launch(void* const* d_in, const int* in_sizes, int n_in,
                              void* d_out, int out_size) {
    const float* x    = (const float*)d_in[0];
    const float* w1   = (const float*)d_in[1];
    const float* bc1  = (const float*)d_in[2];
    const float* w2   = (const float*)d_in[3];
    const float* bc2  = (const float*)d_in[4];
    const float* w3   = (const float*)d_in[5];
    const float* bc3  = (const float*)d_in[6];
    const float* w_ih = (const float*)d_in[7];
    const float* w_hh = (const float*)d_in[8];
    const float* b_ih = (const float*)d_in[9];
    const float* b_hh = (const float*)d_in[10];
    const float* w_y1 = (const float*)d_in[11];
    const float* b_y1 = (const float*)d_in[12];
    const float* w_y2 = (const float*)d_in[13];
    const float* b_y2 = (const float*)d_in[14];

    float *W21, *W321p, *beff, *xwp;
    __half *xh, *xh4, *wihh, *Aimg, *c3h;
    cudaGetSymbolAddress((void**)&W21,   g_W21);
    cudaGetSymbolAddress((void**)&W321p, g_W321p);
    cudaGetSymbolAddress((void**)&beff,  g_beff);
    cudaGetSymbolAddress((void**)&xwp,   g_xwp);
    cudaGetSymbolAddress((void**)&xh,    g_xh);
    cudaGetSymbolAddress((void**)&xh4,   g_xh4);
    cudaGetSymbolAddress((void**)&wihh,  g_wihh);
    cudaGetSymbolAddress((void**)&Aimg,  g_Aimg);
    cudaGetSymbolAddress((void**)&c3h,   g_c3h);

    cudaFuncSetAttribute(conv_hmma, cudaFuncAttributeMaxDynamicSharedMemorySize, CONV_SMEM);
    cudaFuncSetAttribute(gemm_xw_hmma, cudaFuncAttributeMaxDynamicSharedMemorySize, XW_SMEM);

    // L1: cvt_x (+ shifted copy) + cvt_wih + compose21 + fold_bias (fused)
    prep1<<<CVT_BLOCKS + WIH_BLOCKS + C21_BLOCKS + 1, 256>>>(
        x, xh, xh4, w_ih, wihh, w1, w2, w3, bc1, bc2, bc3, W21, beff);
    // L2: compose321 partials
    compose321_sk<<<(40000 + 127) / 128, 128>>>(w3, W21, W321p);
    // L3: A-image build + partial reduce
    prep_A_red<<<(NCH_CHUNK * 112 * 128 + 255) / 256, 256>>>(W321p, Aimg);
    // L4: conv (profiled slot) — R13 proven config, 2 CTAs/SM
    conv_hmma<<<dim3(CONV_NTILE, BATCH), 256, CONV_SMEM>>>(xh, xh4, Aimg, beff, c3h);
    // L5: GRU input GEMM (split-K partials)
    gemm_xw_hmma<<<dim3(13, 3, XW_SPLITK), 256, XW_SMEM>>>(c3h, wihh, xwp);
    // L6: GRU + heads with fused split-K reduce
    gru_kernel<<<BATCH, 320>>>(xwp, b_ih, w_hh, b_hh, w_y1, b_y1, w_y2, b_y2, (float*)d_out);
}